// round 5
// baseline (speedup 1.0000x reference)
#include <cuda_runtime.h>
#include <cuda_bf16.h>
#include <math.h>
#include <stdint.h>

#define N_NODES 100000
#define N_EDGES 1600000
#define N_GRAPHS 64
#define EPSF 1e-7f

#define SCAN_B 1024
#define NB_SCAN ((N_NODES + SCAN_B - 1) / SCAN_B)   // 98

// ---------------- scratch (device globals, device-side access ONLY) --------
__device__ int   g_deg[N_NODES];
__device__ int   g_rowstart[N_NODES];
__device__ int   g_cursor[N_NODES];
__device__ int   g_csr_src[N_EDGES];
__device__ int   g_blocksums[128];
__device__ int   g_gstart[N_GRAPHS + 1];
// fp32 GEMM output (layer i) -> input of next agg; final layer -> pool
__device__ __align__(16) float g_bufC[(size_t)N_NODES * 192];
// split-bf16 activations (GEMM A operand), row stride = layer K
__device__ __align__(16) __nv_bfloat16 g_a1[(size_t)N_NODES * 192];
__device__ __align__(16) __nv_bfloat16 g_a2[(size_t)N_NODES * 192];
// split-bf16 transposed weights [DO][K]
__device__ __align__(16) __nv_bfloat16 g_w1t[192 * 192];
__device__ __align__(16) __nv_bfloat16 g_w2t[192 * 192];
__device__ float g_pool_sum[N_GRAPHS * 128];

__device__ __forceinline__ uint32_t packbf(float a, float b) {
    __nv_bfloat162 t = __floats2bfloat162_rn(a, b);
    return *(uint32_t*)&t;
}

// ---------------- CSR build ----------------
__global__ void k_zero() {
    int i = blockIdx.x * blockDim.x + threadIdx.x;
    if (i < N_NODES) g_deg[i] = 0;
    if (i < N_GRAPHS * 128) g_pool_sum[i] = 0.f;
}

__global__ void k_hist(const int* __restrict__ dst) {
    int i = blockIdx.x * blockDim.x + threadIdx.x;
    if (i < N_EDGES) atomicAdd(&g_deg[dst[i]], 1);
}

__global__ void k_scan1() {
    int idx = blockIdx.x * SCAN_B + threadIdx.x;
    int v = (idx < N_NODES) ? g_deg[idx] : 0;
    int lane = threadIdx.x & 31, w = threadIdx.x >> 5;
    int x = v;
    #pragma unroll
    for (int o = 1; o < 32; o <<= 1) {
        int t = __shfl_up_sync(0xffffffffu, x, o);
        if (lane >= o) x += t;
    }
    __shared__ int wsum[32];
    if (lane == 31) wsum[w] = x;
    __syncthreads();
    if (w == 0) {
        int y = wsum[lane];
        #pragma unroll
        for (int o = 1; o < 32; o <<= 1) {
            int t = __shfl_up_sync(0xffffffffu, y, o);
            if (lane >= o) y += t;
        }
        wsum[lane] = y;
    }
    __syncthreads();
    int incl = x + (w > 0 ? wsum[w - 1] : 0);
    if (idx < N_NODES) g_rowstart[idx] = incl - v;
    if (threadIdx.x == SCAN_B - 1) g_blocksums[blockIdx.x] = incl;
}

__global__ void k_scan2() {
    int t = threadIdx.x;
    int v = (t < NB_SCAN) ? g_blocksums[t] : 0;
    int lane = t & 31, w = t >> 5;
    int x = v;
    #pragma unroll
    for (int o = 1; o < 32; o <<= 1) {
        int tt = __shfl_up_sync(0xffffffffu, x, o);
        if (lane >= o) x += tt;
    }
    __shared__ int ws[4];
    if (lane == 31) ws[w] = x;
    __syncthreads();
    if (t == 0) {
        int a = 0;
        #pragma unroll
        for (int i = 0; i < 4; i++) { int tmp = ws[i]; ws[i] = a; a += tmp; }
    }
    __syncthreads();
    int incl = x + ws[w];
    if (t < 128) g_blocksums[t] = incl - v;
}

__global__ void k_scan3() {
    int idx = blockIdx.x * SCAN_B + threadIdx.x;
    if (idx < N_NODES) {
        int r = g_rowstart[idx] + g_blocksums[idx >> 10];
        g_rowstart[idx] = r;
        g_cursor[idx] = r;
    }
}

__global__ void k_fill(const int* __restrict__ src, const int* __restrict__ dst) {
    int i = blockIdx.x * blockDim.x + threadIdx.x;
    if (i < N_EDGES) {
        int p = atomicAdd(&g_cursor[dst[i]], 1);
        g_csr_src[p] = src[i];
    }
}

// graph boundaries from sorted batch: g_gstart[g] = first node of graph g
__global__ void k_gstart(const int* __restrict__ batch) {
    int i = blockIdx.x * blockDim.x + threadIdx.x;
    if (i >= N_NODES) return;
    int b = batch[i];
    int bp = (i == 0) ? -1 : batch[i - 1];
    for (int g = bp + 1; g <= b; g++) g_gstart[g] = i;
    if (i == N_NODES - 1)
        for (int g = b + 1; g <= N_GRAPHS; g++) g_gstart[g] = N_NODES;
}

// ---------------- aggregation: y = x + segsum(relu(x[src])) + deg*eps ------
// one warp/node, float4 gather unrolled x4 (MLP), emits split-bf16
template <int D>
__global__ void k_agg(const float* __restrict__ xext) {
    int gw = (blockIdx.x * blockDim.x + threadIdx.x) >> 5;
    if (gw >= N_NODES) return;
    int lane = threadIdx.x & 31;
    constexpr int NC = D / 4;
    const float4* Xv = (const float4*)(xext ? xext : (const float*)g_bufC);

    float4 pa = make_float4(0.f, 0.f, 0.f, 0.f);
    float4 pb = make_float4(0.f, 0.f, 0.f, 0.f);
    float4 qa = make_float4(0.f, 0.f, 0.f, 0.f);
    float4 qb = make_float4(0.f, 0.f, 0.f, 0.f);

    int start = g_rowstart[gw];
    int deg = g_deg[gw];

    for (int base = 0; base < deg; base += 32) {
        int myidx = (base + lane < deg) ? g_csr_src[start + base + lane] : 0;
        int cnt = min(32, deg - base);
        int e = 0;
        for (; e + 4 <= cnt; e += 4) {
            int s0 = __shfl_sync(0xffffffffu, myidx, e);
            int s1 = __shfl_sync(0xffffffffu, myidx, e + 1);
            int s2 = __shfl_sync(0xffffffffu, myidx, e + 2);
            int s3 = __shfl_sync(0xffffffffu, myidx, e + 3);
            const float4* r0 = Xv + (size_t)s0 * NC;
            const float4* r1 = Xv + (size_t)s1 * NC;
            const float4* r2 = Xv + (size_t)s2 * NC;
            const float4* r3 = Xv + (size_t)s3 * NC;
            float4 v0 = __ldg(r0 + lane);
            float4 v1 = __ldg(r1 + lane);
            float4 v2 = __ldg(r2 + lane);
            float4 v3 = __ldg(r3 + lane);
            float4 w0, w1, w2, w3;
            if (D == 192 && lane < 16) {
                w0 = __ldg(r0 + 32 + lane);
                w1 = __ldg(r1 + 32 + lane);
                w2 = __ldg(r2 + 32 + lane);
                w3 = __ldg(r3 + 32 + lane);
            }
            pa.x += fmaxf(v0.x, 0.f); pa.y += fmaxf(v0.y, 0.f);
            pa.z += fmaxf(v0.z, 0.f); pa.w += fmaxf(v0.w, 0.f);
            qa.x += fmaxf(v1.x, 0.f); qa.y += fmaxf(v1.y, 0.f);
            qa.z += fmaxf(v1.z, 0.f); qa.w += fmaxf(v1.w, 0.f);
            pa.x += fmaxf(v2.x, 0.f); pa.y += fmaxf(v2.y, 0.f);
            pa.z += fmaxf(v2.z, 0.f); pa.w += fmaxf(v2.w, 0.f);
            qa.x += fmaxf(v3.x, 0.f); qa.y += fmaxf(v3.y, 0.f);
            qa.z += fmaxf(v3.z, 0.f); qa.w += fmaxf(v3.w, 0.f);
            if (D == 192 && lane < 16) {
                pb.x += fmaxf(w0.x, 0.f); pb.y += fmaxf(w0.y, 0.f);
                pb.z += fmaxf(w0.z, 0.f); pb.w += fmaxf(w0.w, 0.f);
                qb.x += fmaxf(w1.x, 0.f); qb.y += fmaxf(w1.y, 0.f);
                qb.z += fmaxf(w1.z, 0.f); qb.w += fmaxf(w1.w, 0.f);
                pb.x += fmaxf(w2.x, 0.f); pb.y += fmaxf(w2.y, 0.f);
                pb.z += fmaxf(w2.z, 0.f); pb.w += fmaxf(w2.w, 0.f);
                qb.x += fmaxf(w3.x, 0.f); qb.y += fmaxf(w3.y, 0.f);
                qb.z += fmaxf(w3.z, 0.f); qb.w += fmaxf(w3.w, 0.f);
            }
        }
        for (; e < cnt; e++) {
            int s = __shfl_sync(0xffffffffu, myidx, e);
            const float4* row = Xv + (size_t)s * NC;
            float4 v = __ldg(row + lane);
            pa.x += fmaxf(v.x, 0.f); pa.y += fmaxf(v.y, 0.f);
            pa.z += fmaxf(v.z, 0.f); pa.w += fmaxf(v.w, 0.f);
            if (D == 192 && lane < 16) {
                float4 w = __ldg(row + 32 + lane);
                pb.x += fmaxf(w.x, 0.f); pb.y += fmaxf(w.y, 0.f);
                pb.z += fmaxf(w.z, 0.f); pb.w += fmaxf(w.w, 0.f);
            }
        }
    }
    pa.x += qa.x; pa.y += qa.y; pa.z += qa.z; pa.w += qa.w;
    pb.x += qb.x; pb.y += qb.y; pb.z += qb.z; pb.w += qb.w;

    const float4* xr = Xv + (size_t)gw * NC;
    float ep = (float)deg * EPSF;

    float4 xv = __ldg(xr + lane);
    float y0 = xv.x + pa.x + ep, y1 = xv.y + pa.y + ep;
    float y2 = xv.z + pa.z + ep, y3 = xv.w + pa.w + ep;
    {
        uint32_t h0 = packbf(y0, y1), h1 = packbf(y2, y3);
        __nv_bfloat162 hh0 = *(__nv_bfloat162*)&h0, hh1 = *(__nv_bfloat162*)&h1;
        float2 f0 = __bfloat1622float2(hh0), f1 = __bfloat1622float2(hh1);
        uint32_t l0 = packbf(y0 - f0.x, y1 - f0.y), l1 = packbf(y2 - f1.x, y3 - f1.y);
        size_t off = (size_t)gw * D + lane * 4;
        *(uint2*)((char*)g_a1 + off * 2) = make_uint2(h0, h1);
        *(uint2*)((char*)g_a2 + off * 2) = make_uint2(l0, l1);
    }
    if (D == 192 && lane < 16) {
        float4 xw = __ldg(xr + 32 + lane);
        float z0 = xw.x + pb.x + ep, z1 = xw.y + pb.y + ep;
        float z2 = xw.z + pb.z + ep, z3 = xw.w + pb.w + ep;
        uint32_t h0 = packbf(z0, z1), h1 = packbf(z2, z3);
        __nv_bfloat162 hh0 = *(__nv_bfloat162*)&h0, hh1 = *(__nv_bfloat162*)&h1;
        float2 f0 = __bfloat1622float2(hh0), f1 = __bfloat1622float2(hh1);
        uint32_t l0 = packbf(z0 - f0.x, z1 - f0.y), l1 = packbf(z2 - f1.x, z3 - f1.y);
        size_t off = (size_t)gw * D + 128 + lane * 4;
        *(uint2*)((char*)g_a1 + off * 2) = make_uint2(h0, h1);
        *(uint2*)((char*)g_a2 + off * 2) = make_uint2(l0, l1);
    }
}

// ---------------- weight prep: W[K,DO] f32 -> split bf16 [DO][K] -----------
__global__ void k_wprep(const float* __restrict__ W, int K, int DO) {
    int i = blockIdx.x * blockDim.x + threadIdx.x;
    if (i < K * DO) {
        int k = i / DO, n = i % DO;
        float w = W[i];
        __nv_bfloat16 h = __float2bfloat16(w);
        float r = w - __bfloat162float(h);
        g_w1t[n * K + k] = h;
        g_w2t[n * K + k] = __float2bfloat16(r);
    }
}

// ---------------- HMMA GEMM v2: g_bufC[N,DO] = (A1+A2)[N,K] @ Wt + b -------
// CTA 128 x DO (full N). Warps: 2(M) x DO/64(N), warp tile 64x64.
#define MMA_BF16(d, a, b0_, b1_) \
    asm volatile("mma.sync.aligned.m16n8k16.row.col.f32.bf16.bf16.f32 " \
        "{%0,%1,%2,%3}, {%4,%5,%6,%7}, {%8,%9}, {%0,%1,%2,%3};" \
        : "+f"((d)[0]), "+f"((d)[1]), "+f"((d)[2]), "+f"((d)[3]) \
        : "r"((a)[0]), "r"((a)[1]), "r"((a)[2]), "r"((a)[3]), \
          "r"(b0_), "r"(b1_))

template <int K, int DO>
__global__ void k_gemm2(const float* __restrict__ bias) {
    constexpr int NTHREADS = DO;           // 2 * (DO/64) warps * 32 = DO
    float* C = g_bufC;
    extern __shared__ char sm[];
    char* As1 = sm;
    char* As2 = sm + 128 * 80;
    char* Bs1 = sm + 2 * 128 * 80;
    char* Bs2 = sm + 2 * 128 * 80 + DO * 80;

    int tid = threadIdx.x;
    int lane = tid & 31, wid = tid >> 5;
    int g = lane >> 2, t = lane & 3;
    int wm = wid & 1;        // 2 M-warps (64 rows each)
    int wn = wid >> 1;       // DO/64 N-warps (64 cols each)
    int bm = blockIdx.x * 128;

    float acc[4][8][4];
    #pragma unroll
    for (int i = 0; i < 4; i++)
        #pragma unroll
        for (int j = 0; j < 8; j++)
            #pragma unroll
            for (int q = 0; q < 4; q++) acc[i][j][q] = 0.f;

    constexpr int NCHUNK = K / 32;
    for (int c = 0; c < NCHUNK; c++) {
        // A: 128 rows x 32 bf16 per split -> 512 uint4 each
        for (int i = tid; i < 512; i += NTHREADS) {
            int row = i >> 2, ch = i & 3;
            int grow = bm + row;
            uint4 v1 = make_uint4(0, 0, 0, 0), v2 = v1;
            if (grow < N_NODES) {
                size_t gb = ((size_t)grow * K + c * 32) * 2 + ch * 16;
                v1 = __ldg((const uint4*)((const char*)g_a1 + gb));
                v2 = __ldg((const uint4*)((const char*)g_a2 + gb));
            }
            *(uint4*)(As1 + row * 80 + ch * 16) = v1;
            *(uint4*)(As2 + row * 80 + ch * 16) = v2;
        }
        // B: DO rows x 32 bf16 per split
        for (int i = tid; i < DO * 4; i += NTHREADS) {
            int n = i >> 2, ch = i & 3;
            size_t gb = ((size_t)n * K + c * 32) * 2 + ch * 16;
            *(uint4*)(Bs1 + n * 80 + ch * 16) = __ldg((const uint4*)((const char*)g_w1t + gb));
            *(uint4*)(Bs2 + n * 80 + ch * 16) = __ldg((const uint4*)((const char*)g_w2t + gb));
        }
        __syncthreads();

        #pragma unroll
        for (int ks = 0; ks < 2; ks++) {
            int kb = ks * 32;
            uint32_t a1f[4][4], a2f[4][4];
            #pragma unroll
            for (int mt = 0; mt < 4; mt++) {
                int rb = (wm * 64 + mt * 16 + g) * 80 + kb + t * 4;
                a1f[mt][0] = *(const uint32_t*)(As1 + rb);
                a1f[mt][1] = *(const uint32_t*)(As1 + rb + 8 * 80);
                a1f[mt][2] = *(const uint32_t*)(As1 + rb + 16);
                a1f[mt][3] = *(const uint32_t*)(As1 + rb + 8 * 80 + 16);
                a2f[mt][0] = *(const uint32_t*)(As2 + rb);
                a2f[mt][1] = *(const uint32_t*)(As2 + rb + 8 * 80);
                a2f[mt][2] = *(const uint32_t*)(As2 + rb + 16);
                a2f[mt][3] = *(const uint32_t*)(As2 + rb + 8 * 80 + 16);
            }
            #pragma unroll
            for (int nt = 0; nt < 8; nt++) {
                int nb = (wn * 64 + nt * 8 + g) * 80 + kb + t * 4;
                uint32_t b10 = *(const uint32_t*)(Bs1 + nb);
                uint32_t b11 = *(const uint32_t*)(Bs1 + nb + 16);
                uint32_t b20 = *(const uint32_t*)(Bs2 + nb);
                uint32_t b21 = *(const uint32_t*)(Bs2 + nb + 16);
                #pragma unroll
                for (int mt = 0; mt < 4; mt++) {
                    MMA_BF16(acc[mt][nt], a1f[mt], b10, b11);
                    MMA_BF16(acc[mt][nt], a1f[mt], b20, b21);
                    MMA_BF16(acc[mt][nt], a2f[mt], b10, b11);
                }
            }
        }
        __syncthreads();
    }

    // epilogue
    #pragma unroll
    for (int nt = 0; nt < 8; nt++) {
        int col = wn * 64 + nt * 8 + 2 * t;
        float2 bv = *(const float2*)(bias + col);
        #pragma unroll
        for (int mt = 0; mt < 4; mt++) {
            int r0 = bm + wm * 64 + mt * 16 + g;
            if (r0 < N_NODES) {
                float2 o = make_float2(acc[mt][nt][0] + bv.x, acc[mt][nt][1] + bv.y);
                *(float2*)(C + (size_t)r0 * DO + col) = o;
            }
            int r1 = r0 + 8;
            if (r1 < N_NODES) {
                float2 o = make_float2(acc[mt][nt][2] + bv.x, acc[mt][nt][3] + bv.y);
                *(float2*)(C + (size_t)r1 * DO + col) = o;
            }
        }
    }
}

// ---------------- pooling (sorted batch -> segment sums, no atomics) -------
__global__ void k_pool() {
    const float* H = g_bufC;                 // final layer output, d=128
    int g = blockIdx.x, chunk = blockIdx.y;  // 64 x 4
    int s = g_gstart[g], e = g_gstart[g + 1];
    int len = e - s;
    int n0 = s + (len * chunk) / 4;
    int n1 = s + (len * (chunk + 1)) / 4;
    int f = threadIdx.x;                     // 128 features
    float a0 = 0.f, a1 = 0.f, a2 = 0.f, a3 = 0.f;
    int n = n0;
    for (; n + 4 <= n1; n += 4) {
        a0 += __ldg(H + (size_t)(n + 0) * 128 + f);
        a1 += __ldg(H + (size_t)(n + 1) * 128 + f);
        a2 += __ldg(H + (size_t)(n + 2) * 128 + f);
        a3 += __ldg(H + (size_t)(n + 3) * 128 + f);
    }
    for (; n < n1; n++) a0 += __ldg(H + (size_t)n * 128 + f);
    float acc = (a0 + a1) + (a2 + a3);
    atomicAdd(&g_pool_sum[g * 128 + f], acc);
}

__global__ void k_head(const float* __restrict__ Wfc, const float* __restrict__ bfc,
                       float* __restrict__ out) {
    __shared__ float s_logit[N_GRAPHS][10];
    __shared__ float s_lse[N_GRAPHS];
    int tid = threadIdx.x;                   // 640 threads
    int g = tid / 10, j = tid % 10;
    float cnt = fmaxf((float)(g_gstart[g + 1] - g_gstart[g]), 1.f);
    float acc = bfc[j];
    #pragma unroll 8
    for (int f = 0; f < 128; f++)
        acc += (g_pool_sum[g * 128 + f] / cnt) * Wfc[f * 10 + j];
    s_logit[g][j] = acc;
    __syncthreads();
    if (j == 0) {
        float m = -1e30f;
        #pragma unroll
        for (int t = 0; t < 10; t++) m = fmaxf(m, s_logit[g][t]);
        float s = 0.f;
        #pragma unroll
        for (int t = 0; t < 10; t++) s += expf(s_logit[g][t] - m);
        s_lse[g] = m + logf(s);
    }
    __syncthreads();
    out[g * 10 + j] = s_logit[g][j] - s_lse[g];
}

// ---------------- launch ----------------
extern "C" void kernel_launch(void* const* d_in, const int* in_sizes, int n_in,
                              void* d_out, int out_size) {
    const float* x   = (const float*)d_in[0];
    const float* W0  = (const float*)d_in[1];
    const float* b0  = (const float*)d_in[2];
    const float* W1  = (const float*)d_in[3];
    const float* b1  = (const float*)d_in[4];
    const float* W2  = (const float*)d_in[5];
    const float* b2  = (const float*)d_in[6];
    const float* W3  = (const float*)d_in[7];
    const float* b3  = (const float*)d_in[8];
    const float* Wfc = (const float*)d_in[9];
    const float* bfc = (const float*)d_in[10];
    const int* ei    = (const int*)d_in[11];
    const int* batch = (const int*)d_in[12];
    const int* src = ei;
    const int* dst = ei + N_EDGES;
    float* out = (float*)d_out;

    const int SMEM_192 = 2 * 128 * 80 + 2 * 192 * 80;  // 51200
    const int SMEM_128 = 2 * 128 * 80 + 2 * 128 * 80;  // 40960
    cudaFuncSetAttribute(k_gemm2<128, 192>, cudaFuncAttributeMaxDynamicSharedMemorySize, SMEM_192);
    cudaFuncSetAttribute(k_gemm2<192, 192>, cudaFuncAttributeMaxDynamicSharedMemorySize, SMEM_192);
    cudaFuncSetAttribute(k_gemm2<192, 128>, cudaFuncAttributeMaxDynamicSharedMemorySize, SMEM_128);

    // CSR build
    k_zero<<<(N_NODES + 255) / 256, 256>>>();
    k_hist<<<(N_EDGES + 255) / 256, 256>>>(dst);
    k_scan1<<<NB_SCAN, SCAN_B>>>();
    k_scan2<<<1, 128>>>();
    k_scan3<<<NB_SCAN, SCAN_B>>>();
    k_fill<<<(N_EDGES + 255) / 256, 256>>>(src, dst);
    k_gstart<<<(N_NODES + 255) / 256, 256>>>(batch);

    int agg_blocks = (N_NODES * 32 + 255) / 256;
    int gemm_grid = (N_NODES + 127) / 128;

    // layer 1: x(128) -> agg(split bf16) -> gemm(128->192) -> g_bufC
    k_wprep<<<(128 * 192 + 255) / 256, 256>>>(W0, 128, 192);
    k_agg<128><<<agg_blocks, 256>>>(x);
    k_gemm2<128, 192><<<gemm_grid, 192, SMEM_192>>>(b0);
    // layer 2
    k_wprep<<<(192 * 192 + 255) / 256, 256>>>(W1, 192, 192);
    k_agg<192><<<agg_blocks, 256>>>(nullptr);
    k_gemm2<192, 192><<<gemm_grid, 192, SMEM_192>>>(b1);
    // layer 3
    k_wprep<<<(192 * 192 + 255) / 256, 256>>>(W2, 192, 192);
    k_agg<192><<<agg_blocks, 256>>>(nullptr);
    k_gemm2<192, 192><<<gemm_grid, 192, SMEM_192>>>(b2);
    // layer 4
    k_wprep<<<(192 * 128 + 255) / 256, 256>>>(W3, 192, 128);
    k_agg<192><<<agg_blocks, 256>>>(nullptr);
    k_gemm2<192, 128><<<gemm_grid, 128, SMEM_128>>>(b3);

    // pooling + head
    dim3 pool_grid(N_GRAPHS, 4);
    k_pool<<<pool_grid, 128>>>();
    k_head<<<1, 640>>>(Wfc, bfc, out);
}

// round 6
// speedup vs baseline: 1.0920x; 1.0920x over previous
#include <cuda_runtime.h>
#include <cuda_bf16.h>
#include <math.h>
#include <stdint.h>

#define N_NODES 100000
#define N_EDGES 1600000
#define N_GRAPHS 64
#define EPSF 1e-7f

#define SCAN_B 1024
#define NB_SCAN ((N_NODES + SCAN_B - 1) / SCAN_B)   // 98

// ---------------- scratch (device globals, device-side access ONLY) --------
__device__ int   g_deg[N_NODES];
__device__ int   g_rowstart[N_NODES];
__device__ int   g_cursor[N_NODES];
__device__ int   g_csr_src[N_EDGES];
__device__ int   g_blocksums[128];
__device__ int   g_gstart[N_GRAPHS + 1];
// fp32 GEMM output (layer i) -> input of next agg; final layer -> pool
__device__ __align__(16) float g_bufC[(size_t)N_NODES * 192];
// split-bf16 activations (GEMM A operand), row stride = layer K
__device__ __align__(16) __nv_bfloat16 g_a1[(size_t)N_NODES * 192];
__device__ __align__(16) __nv_bfloat16 g_a2[(size_t)N_NODES * 192];
// split-bf16 transposed weights [DO][K]
__device__ __align__(16) __nv_bfloat16 g_w1t[192 * 192];
__device__ __align__(16) __nv_bfloat16 g_w2t[192 * 192];
// pool partials: [chunk][graph][feature], summed in head (no atomics)
__device__ float g_pool_sum4[4 * N_GRAPHS * 128];

__device__ __forceinline__ uint32_t packbf(float a, float b) {
    __nv_bfloat162 t = __floats2bfloat162_rn(a, b);
    return *(uint32_t*)&t;
}

// ---------------- CSR build ----------------
__global__ void k_zero() {
    int i = blockIdx.x * blockDim.x + threadIdx.x;
    if (i < N_NODES) g_deg[i] = 0;
}

__global__ void k_hist(const int* __restrict__ dst) {
    int i = blockIdx.x * blockDim.x + threadIdx.x;
    if (i < N_EDGES) atomicAdd(&g_deg[dst[i]], 1);
}

__global__ void k_scan1() {
    int idx = blockIdx.x * SCAN_B + threadIdx.x;
    int v = (idx < N_NODES) ? g_deg[idx] : 0;
    int lane = threadIdx.x & 31, w = threadIdx.x >> 5;
    int x = v;
    #pragma unroll
    for (int o = 1; o < 32; o <<= 1) {
        int t = __shfl_up_sync(0xffffffffu, x, o);
        if (lane >= o) x += t;
    }
    __shared__ int wsum[32];
    if (lane == 31) wsum[w] = x;
    __syncthreads();
    if (w == 0) {
        int y = wsum[lane];
        #pragma unroll
        for (int o = 1; o < 32; o <<= 1) {
            int t = __shfl_up_sync(0xffffffffu, y, o);
            if (lane >= o) y += t;
        }
        wsum[lane] = y;
    }
    __syncthreads();
    int incl = x + (w > 0 ? wsum[w - 1] : 0);
    if (idx < N_NODES) g_rowstart[idx] = incl - v;
    if (threadIdx.x == SCAN_B - 1) g_blocksums[blockIdx.x] = incl;
}

__global__ void k_scan2() {
    int t = threadIdx.x;
    int v = (t < NB_SCAN) ? g_blocksums[t] : 0;
    int lane = t & 31, w = t >> 5;
    int x = v;
    #pragma unroll
    for (int o = 1; o < 32; o <<= 1) {
        int tt = __shfl_up_sync(0xffffffffu, x, o);
        if (lane >= o) x += tt;
    }
    __shared__ int ws[4];
    if (lane == 31) ws[w] = x;
    __syncthreads();
    if (t == 0) {
        int a = 0;
        #pragma unroll
        for (int i = 0; i < 4; i++) { int tmp = ws[i]; ws[i] = a; a += tmp; }
    }
    __syncthreads();
    int incl = x + ws[w];
    if (t < 128) g_blocksums[t] = incl - v;
}

__global__ void k_scan3() {
    int idx = blockIdx.x * SCAN_B + threadIdx.x;
    if (idx < N_NODES) {
        int r = g_rowstart[idx] + g_blocksums[idx >> 10];
        g_rowstart[idx] = r;
        g_cursor[idx] = r;
    }
}

__global__ void k_fill(const int* __restrict__ src, const int* __restrict__ dst) {
    int i = blockIdx.x * blockDim.x + threadIdx.x;
    if (i < N_EDGES) {
        int p = atomicAdd(&g_cursor[dst[i]], 1);
        g_csr_src[p] = src[i];
    }
}

// graph boundaries from sorted batch: g_gstart[g] = first node of graph g
__global__ void k_gstart(const int* __restrict__ batch) {
    int i = blockIdx.x * blockDim.x + threadIdx.x;
    if (i >= N_NODES) return;
    int b = batch[i];
    int bp = (i == 0) ? -1 : batch[i - 1];
    for (int g = bp + 1; g <= b; g++) g_gstart[g] = i;
    if (i == N_NODES - 1)
        for (int g = b + 1; g <= N_GRAPHS; g++) g_gstart[g] = N_NODES;
}

// ---------------- aggregation: y = x + segsum(relu(x[src])) + deg*eps ------
// one warp/node, float4 gather unrolled x4 (MLP), emits split-bf16
template <int D>
__global__ void k_agg(const float* __restrict__ xext) {
    int gw = (blockIdx.x * blockDim.x + threadIdx.x) >> 5;
    if (gw >= N_NODES) return;
    int lane = threadIdx.x & 31;
    constexpr int NC = D / 4;
    const float4* Xv = (const float4*)(xext ? xext : (const float*)g_bufC);

    float4 pa = make_float4(0.f, 0.f, 0.f, 0.f);
    float4 pb = make_float4(0.f, 0.f, 0.f, 0.f);
    float4 qa = make_float4(0.f, 0.f, 0.f, 0.f);
    float4 qb = make_float4(0.f, 0.f, 0.f, 0.f);

    int start = g_rowstart[gw];
    int deg = g_deg[gw];

    for (int base = 0; base < deg; base += 32) {
        int myidx = (base + lane < deg) ? g_csr_src[start + base + lane] : 0;
        int cnt = min(32, deg - base);
        int e = 0;
        for (; e + 4 <= cnt; e += 4) {
            int s0 = __shfl_sync(0xffffffffu, myidx, e);
            int s1 = __shfl_sync(0xffffffffu, myidx, e + 1);
            int s2 = __shfl_sync(0xffffffffu, myidx, e + 2);
            int s3 = __shfl_sync(0xffffffffu, myidx, e + 3);
            const float4* r0 = Xv + (size_t)s0 * NC;
            const float4* r1 = Xv + (size_t)s1 * NC;
            const float4* r2 = Xv + (size_t)s2 * NC;
            const float4* r3 = Xv + (size_t)s3 * NC;
            float4 v0 = __ldg(r0 + lane);
            float4 v1 = __ldg(r1 + lane);
            float4 v2 = __ldg(r2 + lane);
            float4 v3 = __ldg(r3 + lane);
            float4 w0, w1, w2, w3;
            if (D == 192 && lane < 16) {
                w0 = __ldg(r0 + 32 + lane);
                w1 = __ldg(r1 + 32 + lane);
                w2 = __ldg(r2 + 32 + lane);
                w3 = __ldg(r3 + 32 + lane);
            }
            pa.x += fmaxf(v0.x, 0.f); pa.y += fmaxf(v0.y, 0.f);
            pa.z += fmaxf(v0.z, 0.f); pa.w += fmaxf(v0.w, 0.f);
            qa.x += fmaxf(v1.x, 0.f); qa.y += fmaxf(v1.y, 0.f);
            qa.z += fmaxf(v1.z, 0.f); qa.w += fmaxf(v1.w, 0.f);
            pa.x += fmaxf(v2.x, 0.f); pa.y += fmaxf(v2.y, 0.f);
            pa.z += fmaxf(v2.z, 0.f); pa.w += fmaxf(v2.w, 0.f);
            qa.x += fmaxf(v3.x, 0.f); qa.y += fmaxf(v3.y, 0.f);
            qa.z += fmaxf(v3.z, 0.f); qa.w += fmaxf(v3.w, 0.f);
            if (D == 192 && lane < 16) {
                pb.x += fmaxf(w0.x, 0.f); pb.y += fmaxf(w0.y, 0.f);
                pb.z += fmaxf(w0.z, 0.f); pb.w += fmaxf(w0.w, 0.f);
                qb.x += fmaxf(w1.x, 0.f); qb.y += fmaxf(w1.y, 0.f);
                qb.z += fmaxf(w1.z, 0.f); qb.w += fmaxf(w1.w, 0.f);
                pb.x += fmaxf(w2.x, 0.f); pb.y += fmaxf(w2.y, 0.f);
                pb.z += fmaxf(w2.z, 0.f); pb.w += fmaxf(w2.w, 0.f);
                qb.x += fmaxf(w3.x, 0.f); qb.y += fmaxf(w3.y, 0.f);
                qb.z += fmaxf(w3.z, 0.f); qb.w += fmaxf(w3.w, 0.f);
            }
        }
        for (; e < cnt; e++) {
            int s = __shfl_sync(0xffffffffu, myidx, e);
            const float4* row = Xv + (size_t)s * NC;
            float4 v = __ldg(row + lane);
            pa.x += fmaxf(v.x, 0.f); pa.y += fmaxf(v.y, 0.f);
            pa.z += fmaxf(v.z, 0.f); pa.w += fmaxf(v.w, 0.f);
            if (D == 192 && lane < 16) {
                float4 w = __ldg(row + 32 + lane);
                pb.x += fmaxf(w.x, 0.f); pb.y += fmaxf(w.y, 0.f);
                pb.z += fmaxf(w.z, 0.f); pb.w += fmaxf(w.w, 0.f);
            }
        }
    }
    pa.x += qa.x; pa.y += qa.y; pa.z += qa.z; pa.w += qa.w;
    pb.x += qb.x; pb.y += qb.y; pb.z += qb.z; pb.w += qb.w;

    const float4* xr = Xv + (size_t)gw * NC;
    float ep = (float)deg * EPSF;

    float4 xv = __ldg(xr + lane);
    float y0 = xv.x + pa.x + ep, y1 = xv.y + pa.y + ep;
    float y2 = xv.z + pa.z + ep, y3 = xv.w + pa.w + ep;
    {
        uint32_t h0 = packbf(y0, y1), h1 = packbf(y2, y3);
        __nv_bfloat162 hh0 = *(__nv_bfloat162*)&h0, hh1 = *(__nv_bfloat162*)&h1;
        float2 f0 = __bfloat1622float2(hh0), f1 = __bfloat1622float2(hh1);
        uint32_t l0 = packbf(y0 - f0.x, y1 - f0.y), l1 = packbf(y2 - f1.x, y3 - f1.y);
        size_t off = (size_t)gw * D + lane * 4;
        *(uint2*)((char*)g_a1 + off * 2) = make_uint2(h0, h1);
        *(uint2*)((char*)g_a2 + off * 2) = make_uint2(l0, l1);
    }
    if (D == 192 && lane < 16) {
        float4 xw = __ldg(xr + 32 + lane);
        float z0 = xw.x + pb.x + ep, z1 = xw.y + pb.y + ep;
        float z2 = xw.z + pb.z + ep, z3 = xw.w + pb.w + ep;
        uint32_t h0 = packbf(z0, z1), h1 = packbf(z2, z3);
        __nv_bfloat162 hh0 = *(__nv_bfloat162*)&h0, hh1 = *(__nv_bfloat162*)&h1;
        float2 f0 = __bfloat1622float2(hh0), f1 = __bfloat1622float2(hh1);
        uint32_t l0 = packbf(z0 - f0.x, z1 - f0.y), l1 = packbf(z2 - f1.x, z3 - f1.y);
        size_t off = (size_t)gw * D + 128 + lane * 4;
        *(uint2*)((char*)g_a1 + off * 2) = make_uint2(h0, h1);
        *(uint2*)((char*)g_a2 + off * 2) = make_uint2(l0, l1);
    }
}

// ---------------- weight prep: W[K,DO] f32 -> split bf16 [DO][K] -----------
__global__ void k_wprep(const float* __restrict__ W, int K, int DO) {
    int i = blockIdx.x * blockDim.x + threadIdx.x;
    if (i < K * DO) {
        int k = i / DO, n = i % DO;
        float w = W[i];
        __nv_bfloat16 h = __float2bfloat16(w);
        float r = w - __bfloat162float(h);
        g_w1t[n * K + k] = h;
        g_w2t[n * K + k] = __float2bfloat16(r);
    }
}

// ---------------- HMMA GEMM (R4-proven): C = (A1+A2) @ Wt + b --------------
// mma.sync m16n8k16 bf16, split x3. CTA 128x64, 8 warps (4Mx2N), warp 32x32.
#define MMA_BF16(d, a, b0_, b1_) \
    asm volatile("mma.sync.aligned.m16n8k16.row.col.f32.bf16.bf16.f32 " \
        "{%0,%1,%2,%3}, {%4,%5,%6,%7}, {%8,%9}, {%0,%1,%2,%3};" \
        : "+f"((d)[0]), "+f"((d)[1]), "+f"((d)[2]), "+f"((d)[3]) \
        : "r"((a)[0]), "r"((a)[1]), "r"((a)[2]), "r"((a)[3]), \
          "r"(b0_), "r"(b1_))

template <int K, int DO>
__global__ __launch_bounds__(256) void k_gemm(const float* __restrict__ bias) {
    float* C = g_bufC;
    // 80-byte row stride: fragment LDS bank phase (20g+t)%32 conflict-free
    __shared__ char As1[128 * 80];
    __shared__ char As2[128 * 80];
    __shared__ char Bs1[64 * 80];
    __shared__ char Bs2[64 * 80];

    int tid = threadIdx.x;
    int lane = tid & 31, wid = tid >> 5;
    int g = lane >> 2, t = lane & 3;
    int wm = wid & 3, wn = wid >> 2;
    int bm = blockIdx.x * 128;
    int bn = blockIdx.y * 64;

    float acc[2][4][4];
    #pragma unroll
    for (int i = 0; i < 2; i++)
        #pragma unroll
        for (int j = 0; j < 4; j++)
            #pragma unroll
            for (int q = 0; q < 4; q++) acc[i][j][q] = 0.f;

    constexpr int NCHUNK = K / 32;
    for (int c = 0; c < NCHUNK; c++) {
        // A tiles: 128 rows x 32 bf16 (64B) per split
        #pragma unroll
        for (int i = 0; i < 2; i++) {
            int slot = tid * 2 + i;
            int row = slot >> 2, ch = slot & 3;
            int grow = bm + row;
            uint4 v1 = make_uint4(0, 0, 0, 0), v2 = v1;
            if (grow < N_NODES) {
                size_t gb = ((size_t)grow * K + c * 32) * 2 + ch * 16;
                v1 = __ldg((const uint4*)((const char*)g_a1 + gb));
                v2 = __ldg((const uint4*)((const char*)g_a2 + gb));
            }
            *(uint4*)(As1 + row * 80 + ch * 16) = v1;
            *(uint4*)(As2 + row * 80 + ch * 16) = v2;
        }
        // B tiles: 64 rows x 32 bf16 per split
        {
            int n = tid >> 2, ch = tid & 3;
            size_t gb = ((size_t)(bn + n) * K + c * 32) * 2 + ch * 16;
            *(uint4*)(Bs1 + n * 80 + ch * 16) = __ldg((const uint4*)((const char*)g_w1t + gb));
            *(uint4*)(Bs2 + n * 80 + ch * 16) = __ldg((const uint4*)((const char*)g_w2t + gb));
        }
        __syncthreads();

        #pragma unroll
        for (int ks = 0; ks < 2; ks++) {
            int kb = ks * 32;   // byte offset within row (16 bf16)
            uint32_t a1f[2][4], a2f[2][4];
            #pragma unroll
            for (int mt = 0; mt < 2; mt++) {
                int rb = (wm * 32 + mt * 16 + g) * 80 + kb + t * 4;
                a1f[mt][0] = *(const uint32_t*)(As1 + rb);
                a1f[mt][1] = *(const uint32_t*)(As1 + rb + 8 * 80);
                a1f[mt][2] = *(const uint32_t*)(As1 + rb + 16);
                a1f[mt][3] = *(const uint32_t*)(As1 + rb + 8 * 80 + 16);
                a2f[mt][0] = *(const uint32_t*)(As2 + rb);
                a2f[mt][1] = *(const uint32_t*)(As2 + rb + 8 * 80);
                a2f[mt][2] = *(const uint32_t*)(As2 + rb + 16);
                a2f[mt][3] = *(const uint32_t*)(As2 + rb + 8 * 80 + 16);
            }
            #pragma unroll
            for (int nt = 0; nt < 4; nt++) {
                int nb = (wn * 32 + nt * 8 + g) * 80 + kb + t * 4;
                uint32_t b10 = *(const uint32_t*)(Bs1 + nb);
                uint32_t b11 = *(const uint32_t*)(Bs1 + nb + 16);
                uint32_t b20 = *(const uint32_t*)(Bs2 + nb);
                uint32_t b21 = *(const uint32_t*)(Bs2 + nb + 16);
                #pragma unroll
                for (int mt = 0; mt < 2; mt++) {
                    MMA_BF16(acc[mt][nt], a1f[mt], b10, b11);
                    MMA_BF16(acc[mt][nt], a1f[mt], b20, b21);
                    MMA_BF16(acc[mt][nt], a2f[mt], b10, b11);
                }
            }
        }
        __syncthreads();
    }

    // epilogue
    #pragma unroll
    for (int nt = 0; nt < 4; nt++) {
        int col = bn + wn * 32 + nt * 8 + 2 * t;
        float2 bv = *(const float2*)(bias + col);
        #pragma unroll
        for (int mt = 0; mt < 2; mt++) {
            int r0 = bm + wm * 32 + mt * 16 + g;
            if (r0 < N_NODES) {
                float2 o = make_float2(acc[mt][nt][0] + bv.x, acc[mt][nt][1] + bv.y);
                *(float2*)(C + (size_t)r0 * DO + col) = o;
            }
            int r1 = r0 + 8;
            if (r1 < N_NODES) {
                float2 o = make_float2(acc[mt][nt][2] + bv.x, acc[mt][nt][3] + bv.y);
                *(float2*)(C + (size_t)r1 * DO + col) = o;
            }
        }
    }
}

// ---------------- pooling (sorted batch -> segment sums, atomic-free) ------
__global__ void k_pool() {
    const float* H = g_bufC;                 // final layer output, d=128
    int g = blockIdx.x, chunk = blockIdx.y;  // 64 x 4
    int s = g_gstart[g], e = g_gstart[g + 1];
    int len = e - s;
    int n0 = s + (len * chunk) / 4;
    int n1 = s + (len * (chunk + 1)) / 4;
    int f = threadIdx.x;                     // 128 features
    float a0 = 0.f, a1 = 0.f, a2 = 0.f, a3 = 0.f;
    int n = n0;
    for (; n + 4 <= n1; n += 4) {
        a0 += __ldg(H + (size_t)(n + 0) * 128 + f);
        a1 += __ldg(H + (size_t)(n + 1) * 128 + f);
        a2 += __ldg(H + (size_t)(n + 2) * 128 + f);
        a3 += __ldg(H + (size_t)(n + 3) * 128 + f);
    }
    for (; n < n1; n++) a0 += __ldg(H + (size_t)n * 128 + f);
    g_pool_sum4[(chunk * N_GRAPHS + g) * 128 + f] = (a0 + a1) + (a2 + a3);
}

__global__ void k_head(const float* __restrict__ Wfc, const float* __restrict__ bfc,
                       float* __restrict__ out) {
    __shared__ float s_logit[N_GRAPHS][10];
    __shared__ float s_lse[N_GRAPHS];
    int tid = threadIdx.x;                   // 640 threads
    int g = tid / 10, j = tid % 10;
    float cnt = fmaxf((float)(g_gstart[g + 1] - g_gstart[g]), 1.f);
    float acc = bfc[j];
    #pragma unroll 8
    for (int f = 0; f < 128; f++) {
        float s = g_pool_sum4[(0 * N_GRAPHS + g) * 128 + f]
                + g_pool_sum4[(1 * N_GRAPHS + g) * 128 + f]
                + g_pool_sum4[(2 * N_GRAPHS + g) * 128 + f]
                + g_pool_sum4[(3 * N_GRAPHS + g) * 128 + f];
        acc += (s / cnt) * Wfc[f * 10 + j];
    }
    s_logit[g][j] = acc;
    __syncthreads();
    if (j == 0) {
        float m = -1e30f;
        #pragma unroll
        for (int t = 0; t < 10; t++) m = fmaxf(m, s_logit[g][t]);
        float s = 0.f;
        #pragma unroll
        for (int t = 0; t < 10; t++) s += expf(s_logit[g][t] - m);
        s_lse[g] = m + logf(s);
    }
    __syncthreads();
    out[g * 10 + j] = s_logit[g][j] - s_lse[g];
}

// ---------------- launch ----------------
extern "C" void kernel_launch(void* const* d_in, const int* in_sizes, int n_in,
                              void* d_out, int out_size) {
    const float* x   = (const float*)d_in[0];
    const float* W0  = (const float*)d_in[1];
    const float* b0  = (const float*)d_in[2];
    const float* W1  = (const float*)d_in[3];
    const float* b1  = (const float*)d_in[4];
    const float* W2  = (const float*)d_in[5];
    const float* b2  = (const float*)d_in[6];
    const float* W3  = (const float*)d_in[7];
    const float* b3  = (const float*)d_in[8];
    const float* Wfc = (const float*)d_in[9];
    const float* bfc = (const float*)d_in[10];
    const int* ei    = (const int*)d_in[11];
    const int* batch = (const int*)d_in[12];
    const int* src = ei;
    const int* dst = ei + N_EDGES;
    float* out = (float*)d_out;

    // CSR build
    k_zero<<<(N_NODES + 255) / 256, 256>>>();
    k_hist<<<(N_EDGES + 255) / 256, 256>>>(dst);
    k_scan1<<<NB_SCAN, SCAN_B>>>();
    k_scan2<<<1, 128>>>();
    k_scan3<<<NB_SCAN, SCAN_B>>>();
    k_fill<<<(N_EDGES + 255) / 256, 256>>>(src, dst);
    k_gstart<<<(N_NODES + 255) / 256, 256>>>(batch);

    int agg_blocks = (N_NODES * 32 + 255) / 256;
    dim3 g192((N_NODES + 127) / 128, 3);
    dim3 g128((N_NODES + 127) / 128, 2);

    // layer 1: x(128) -> agg(split bf16) -> gemm(128->192) -> g_bufC
    k_wprep<<<(128 * 192 + 255) / 256, 256>>>(W0, 128, 192);
    k_agg<128><<<agg_blocks, 256>>>(x);
    k_gemm<128, 192><<<g192, 256>>>(b0);
    // layer 2
    k_wprep<<<(192 * 192 + 255) / 256, 256>>>(W1, 192, 192);
    k_agg<192><<<agg_blocks, 256>>>(nullptr);
    k_gemm<192, 192><<<g192, 256>>>(b1);
    // layer 3
    k_wprep<<<(192 * 192 + 255) / 256, 256>>>(W2, 192, 192);
    k_agg<192><<<agg_blocks, 256>>>(nullptr);
    k_gemm<192, 192><<<g192, 256>>>(b2);
    // layer 4
    k_wprep<<<(192 * 128 + 255) / 256, 256>>>(W3, 192, 128);
    k_agg<192><<<agg_blocks, 256>>>(nullptr);
    k_gemm<192, 128><<<g128, 256>>>(b3);

    // pooling + head
    dim3 pool_grid(N_GRAPHS, 4);
    k_pool<<<pool_grid, 128>>>();
    k_head<<<1, 640>>>(Wfc, bfc, out);
}

// round 7
// speedup vs baseline: 1.1955x; 1.0947x over previous
#include <cuda_runtime.h>
#include <cuda_bf16.h>
#include <math.h>
#include <stdint.h>

#define N_NODES 100000
#define N_EDGES 1600000
#define N_GRAPHS 64
#define EPSF 1e-7f

#define SCAN_B 1024
#define NB_SCAN ((N_NODES + SCAN_B - 1) / SCAN_B)   // 98

// ---------------- scratch (device globals, device-side access ONLY) --------
__device__ int   g_deg[N_NODES];
__device__ int   g_rowstart[N_NODES];
__device__ int   g_cursor[N_NODES];
__device__ int   g_csr_src[N_EDGES];
__device__ int   g_blocksums[128];
__device__ int   g_gstart[N_GRAPHS + 1];
// fp32 GEMM output (layer i) -> input of next agg; final layer -> pool
__device__ __align__(16) float g_bufC[(size_t)N_NODES * 192];
// split-bf16 activations (GEMM A operand), row stride = layer K
__device__ __align__(16) __nv_bfloat16 g_a1[(size_t)N_NODES * 192];
__device__ __align__(16) __nv_bfloat16 g_a2[(size_t)N_NODES * 192];
// split-bf16 transposed weights [DO][K]
__device__ __align__(16) __nv_bfloat16 g_w1t[192 * 192];
__device__ __align__(16) __nv_bfloat16 g_w2t[192 * 192];
// pool partials: [chunk][graph][feature], summed in head (no atomics)
__device__ float g_pool_sum4[4 * N_GRAPHS * 128];

__device__ __forceinline__ uint32_t packbf(float a, float b) {
    __nv_bfloat162 t = __floats2bfloat162_rn(a, b);
    return *(uint32_t*)&t;
}

// ---------------- CSR build ----------------
__global__ void k_zero() {
    int i = blockIdx.x * blockDim.x + threadIdx.x;
    if (i < N_NODES) g_deg[i] = 0;
}

__global__ void k_hist(const int* __restrict__ dst) {
    int i = blockIdx.x * blockDim.x + threadIdx.x;
    if (i < N_EDGES) atomicAdd(&g_deg[dst[i]], 1);
}

__global__ void k_scan1() {
    int idx = blockIdx.x * SCAN_B + threadIdx.x;
    int v = (idx < N_NODES) ? g_deg[idx] : 0;
    int lane = threadIdx.x & 31, w = threadIdx.x >> 5;
    int x = v;
    #pragma unroll
    for (int o = 1; o < 32; o <<= 1) {
        int t = __shfl_up_sync(0xffffffffu, x, o);
        if (lane >= o) x += t;
    }
    __shared__ int wsum[32];
    if (lane == 31) wsum[w] = x;
    __syncthreads();
    if (w == 0) {
        int y = wsum[lane];
        #pragma unroll
        for (int o = 1; o < 32; o <<= 1) {
            int t = __shfl_up_sync(0xffffffffu, y, o);
            if (lane >= o) y += t;
        }
        wsum[lane] = y;
    }
    __syncthreads();
    int incl = x + (w > 0 ? wsum[w - 1] : 0);
    if (idx < N_NODES) g_rowstart[idx] = incl - v;
    if (threadIdx.x == SCAN_B - 1) g_blocksums[blockIdx.x] = incl;
}

__global__ void k_scan2() {
    int t = threadIdx.x;
    int v = (t < NB_SCAN) ? g_blocksums[t] : 0;
    int lane = t & 31, w = t >> 5;
    int x = v;
    #pragma unroll
    for (int o = 1; o < 32; o <<= 1) {
        int tt = __shfl_up_sync(0xffffffffu, x, o);
        if (lane >= o) x += tt;
    }
    __shared__ int ws[4];
    if (lane == 31) ws[w] = x;
    __syncthreads();
    if (t == 0) {
        int a = 0;
        #pragma unroll
        for (int i = 0; i < 4; i++) { int tmp = ws[i]; ws[i] = a; a += tmp; }
    }
    __syncthreads();
    int incl = x + ws[w];
    if (t < 128) g_blocksums[t] = incl - v;
}

__global__ void k_scan3() {
    int idx = blockIdx.x * SCAN_B + threadIdx.x;
    if (idx < N_NODES) {
        int r = g_rowstart[idx] + g_blocksums[idx >> 10];
        g_rowstart[idx] = r;
        g_cursor[idx] = r;
    }
}

__global__ void k_fill(const int* __restrict__ src, const int* __restrict__ dst) {
    int i = blockIdx.x * blockDim.x + threadIdx.x;
    if (i < N_EDGES) {
        int p = atomicAdd(&g_cursor[dst[i]], 1);
        g_csr_src[p] = src[i];
    }
}

// graph boundaries from sorted batch: g_gstart[g] = first node of graph g
__global__ void k_gstart(const int* __restrict__ batch) {
    int i = blockIdx.x * blockDim.x + threadIdx.x;
    if (i >= N_NODES) return;
    int b = batch[i];
    int bp = (i == 0) ? -1 : batch[i - 1];
    for (int g = bp + 1; g <= b; g++) g_gstart[g] = i;
    if (i == N_NODES - 1)
        for (int g = b + 1; g <= N_GRAPHS; g++) g_gstart[g] = N_NODES;
}

// ---------------- aggregation: y = x + segsum(relu(x[src])) + deg*eps ------
// one warp/node, float4 gather (R4-proven simple loop); emits split-bf16
template <int D>
__global__ void k_agg(const float* __restrict__ xext) {
    int gw = (blockIdx.x * blockDim.x + threadIdx.x) >> 5;
    if (gw >= N_NODES) return;
    int lane = threadIdx.x & 31;
    constexpr int NC = D / 4;
    const float4* Xv = (const float4*)(xext ? xext : (const float*)g_bufC);

    float4 a0 = make_float4(0.f, 0.f, 0.f, 0.f);
    float4 a1 = make_float4(0.f, 0.f, 0.f, 0.f);

    int start = g_rowstart[gw];
    int deg = g_deg[gw];

    for (int base = 0; base < deg; base += 32) {
        int myidx = (base + lane < deg) ? g_csr_src[start + base + lane] : 0;
        int cnt = min(32, deg - base);
        for (int e = 0; e < cnt; e++) {
            int s = __shfl_sync(0xffffffffu, myidx, e);
            const float4* row = Xv + (size_t)s * NC;
            float4 v = __ldg(row + lane);
            a0.x += fmaxf(v.x, 0.f); a0.y += fmaxf(v.y, 0.f);
            a0.z += fmaxf(v.z, 0.f); a0.w += fmaxf(v.w, 0.f);
            if (D == 192 && lane < 16) {
                float4 w = __ldg(row + 32 + lane);
                a1.x += fmaxf(w.x, 0.f); a1.y += fmaxf(w.y, 0.f);
                a1.z += fmaxf(w.z, 0.f); a1.w += fmaxf(w.w, 0.f);
            }
        }
    }

    const float4* xr = Xv + (size_t)gw * NC;
    float ep = (float)deg * EPSF;

    float4 xv = __ldg(xr + lane);
    float y0 = xv.x + a0.x + ep, y1 = xv.y + a0.y + ep;
    float y2 = xv.z + a0.z + ep, y3 = xv.w + a0.w + ep;
    {
        uint32_t h0 = packbf(y0, y1), h1 = packbf(y2, y3);
        __nv_bfloat162 hh0 = *(__nv_bfloat162*)&h0, hh1 = *(__nv_bfloat162*)&h1;
        float2 f0 = __bfloat1622float2(hh0), f1 = __bfloat1622float2(hh1);
        uint32_t l0 = packbf(y0 - f0.x, y1 - f0.y), l1 = packbf(y2 - f1.x, y3 - f1.y);
        size_t off = (size_t)gw * D + lane * 4;
        *(uint2*)((char*)g_a1 + off * 2) = make_uint2(h0, h1);
        *(uint2*)((char*)g_a2 + off * 2) = make_uint2(l0, l1);
    }
    if (D == 192 && lane < 16) {
        float4 xw = __ldg(xr + 32 + lane);
        float z0 = xw.x + a1.x + ep, z1 = xw.y + a1.y + ep;
        float z2 = xw.z + a1.z + ep, z3 = xw.w + a1.w + ep;
        uint32_t h0 = packbf(z0, z1), h1 = packbf(z2, z3);
        __nv_bfloat162 hh0 = *(__nv_bfloat162*)&h0, hh1 = *(__nv_bfloat162*)&h1;
        float2 f0 = __bfloat1622float2(hh0), f1 = __bfloat1622float2(hh1);
        uint32_t l0 = packbf(z0 - f0.x, z1 - f0.y), l1 = packbf(z2 - f1.x, z3 - f1.y);
        size_t off = (size_t)gw * D + 128 + lane * 4;
        *(uint2*)((char*)g_a1 + off * 2) = make_uint2(h0, h1);
        *(uint2*)((char*)g_a2 + off * 2) = make_uint2(l0, l1);
    }
}

// ---------------- weight prep: W[K,DO] f32 -> split bf16 [DO][K] -----------
__global__ void k_wprep(const float* __restrict__ W, int K, int DO) {
    int i = blockIdx.x * blockDim.x + threadIdx.x;
    if (i < K * DO) {
        int k = i / DO, n = i % DO;
        float w = W[i];
        __nv_bfloat16 h = __float2bfloat16(w);
        float r = w - __bfloat162float(h);
        g_w1t[n * K + k] = h;
        g_w2t[n * K + k] = __float2bfloat16(r);
    }
}

// ---------------- HMMA GEMM (R4-proven): C = (A1+A2) @ Wt + b --------------
// mma.sync m16n8k16 bf16, split x3. CTA 128x64, 8 warps (4Mx2N), warp 32x32.
#define MMA_BF16(d, a, b0_, b1_) \
    asm volatile("mma.sync.aligned.m16n8k16.row.col.f32.bf16.bf16.f32 " \
        "{%0,%1,%2,%3}, {%4,%5,%6,%7}, {%8,%9}, {%0,%1,%2,%3};" \
        : "+f"((d)[0]), "+f"((d)[1]), "+f"((d)[2]), "+f"((d)[3]) \
        : "r"((a)[0]), "r"((a)[1]), "r"((a)[2]), "r"((a)[3]), \
          "r"(b0_), "r"(b1_))

template <int K, int DO>
__global__ __launch_bounds__(256) void k_gemm(const float* __restrict__ bias) {
    float* C = g_bufC;
    // 80-byte row stride: fragment LDS bank phase (20g+t)%32 conflict-free
    __shared__ char As1[128 * 80];
    __shared__ char As2[128 * 80];
    __shared__ char Bs1[64 * 80];
    __shared__ char Bs2[64 * 80];

    int tid = threadIdx.x;
    int lane = tid & 31, wid = tid >> 5;
    int g = lane >> 2, t = lane & 3;
    int wm = wid & 3, wn = wid >> 2;
    int bm = blockIdx.x * 128;
    int bn = blockIdx.y * 64;

    float acc[2][4][4];
    #pragma unroll
    for (int i = 0; i < 2; i++)
        #pragma unroll
        for (int j = 0; j < 4; j++)
            #pragma unroll
            for (int q = 0; q < 4; q++) acc[i][j][q] = 0.f;

    constexpr int NCHUNK = K / 32;
    for (int c = 0; c < NCHUNK; c++) {
        // A tiles: 128 rows x 32 bf16 (64B) per split
        #pragma unroll
        for (int i = 0; i < 2; i++) {
            int slot = tid * 2 + i;
            int row = slot >> 2, ch = slot & 3;
            int grow = bm + row;
            uint4 v1 = make_uint4(0, 0, 0, 0), v2 = v1;
            if (grow < N_NODES) {
                size_t gb = ((size_t)grow * K + c * 32) * 2 + ch * 16;
                v1 = __ldg((const uint4*)((const char*)g_a1 + gb));
                v2 = __ldg((const uint4*)((const char*)g_a2 + gb));
            }
            *(uint4*)(As1 + row * 80 + ch * 16) = v1;
            *(uint4*)(As2 + row * 80 + ch * 16) = v2;
        }
        // B tiles: 64 rows x 32 bf16 per split
        {
            int n = tid >> 2, ch = tid & 3;
            size_t gb = ((size_t)(bn + n) * K + c * 32) * 2 + ch * 16;
            *(uint4*)(Bs1 + n * 80 + ch * 16) = __ldg((const uint4*)((const char*)g_w1t + gb));
            *(uint4*)(Bs2 + n * 80 + ch * 16) = __ldg((const uint4*)((const char*)g_w2t + gb));
        }
        __syncthreads();

        #pragma unroll
        for (int ks = 0; ks < 2; ks++) {
            int kb = ks * 32;   // byte offset within row (16 bf16)
            uint32_t a1f[2][4], a2f[2][4];
            #pragma unroll
            for (int mt = 0; mt < 2; mt++) {
                int rb = (wm * 32 + mt * 16 + g) * 80 + kb + t * 4;
                a1f[mt][0] = *(const uint32_t*)(As1 + rb);
                a1f[mt][1] = *(const uint32_t*)(As1 + rb + 8 * 80);
                a1f[mt][2] = *(const uint32_t*)(As1 + rb + 16);
                a1f[mt][3] = *(const uint32_t*)(As1 + rb + 8 * 80 + 16);
                a2f[mt][0] = *(const uint32_t*)(As2 + rb);
                a2f[mt][1] = *(const uint32_t*)(As2 + rb + 8 * 80);
                a2f[mt][2] = *(const uint32_t*)(As2 + rb + 16);
                a2f[mt][3] = *(const uint32_t*)(As2 + rb + 8 * 80 + 16);
            }
            #pragma unroll
            for (int nt = 0; nt < 4; nt++) {
                int nb = (wn * 32 + nt * 8 + g) * 80 + kb + t * 4;
                uint32_t b10 = *(const uint32_t*)(Bs1 + nb);
                uint32_t b11 = *(const uint32_t*)(Bs1 + nb + 16);
                uint32_t b20 = *(const uint32_t*)(Bs2 + nb);
                uint32_t b21 = *(const uint32_t*)(Bs2 + nb + 16);
                #pragma unroll
                for (int mt = 0; mt < 2; mt++) {
                    MMA_BF16(acc[mt][nt], a1f[mt], b10, b11);
                    MMA_BF16(acc[mt][nt], a1f[mt], b20, b21);
                    MMA_BF16(acc[mt][nt], a2f[mt], b10, b11);
                }
            }
        }
        __syncthreads();
    }

    // epilogue
    #pragma unroll
    for (int nt = 0; nt < 4; nt++) {
        int col = bn + wn * 32 + nt * 8 + 2 * t;
        float2 bv = *(const float2*)(bias + col);
        #pragma unroll
        for (int mt = 0; mt < 2; mt++) {
            int r0 = bm + wm * 32 + mt * 16 + g;
            if (r0 < N_NODES) {
                float2 o = make_float2(acc[mt][nt][0] + bv.x, acc[mt][nt][1] + bv.y);
                *(float2*)(C + (size_t)r0 * DO + col) = o;
            }
            int r1 = r0 + 8;
            if (r1 < N_NODES) {
                float2 o = make_float2(acc[mt][nt][2] + bv.x, acc[mt][nt][3] + bv.y);
                *(float2*)(C + (size_t)r1 * DO + col) = o;
            }
        }
    }
}

// ---------------- pooling (sorted batch -> segment sums, atomic-free) ------
__global__ void k_pool() {
    const float* H = g_bufC;                 // final layer output, d=128
    int g = blockIdx.x, chunk = blockIdx.y;  // 64 x 4
    int s = g_gstart[g], e = g_gstart[g + 1];
    int len = e - s;
    int n0 = s + (len * chunk) / 4;
    int n1 = s + (len * (chunk + 1)) / 4;
    int f = threadIdx.x;                     // 128 features
    float a0 = 0.f, a1 = 0.f, a2 = 0.f, a3 = 0.f;
    int n = n0;
    for (; n + 4 <= n1; n += 4) {
        a0 += __ldg(H + (size_t)(n + 0) * 128 + f);
        a1 += __ldg(H + (size_t)(n + 1) * 128 + f);
        a2 += __ldg(H + (size_t)(n + 2) * 128 + f);
        a3 += __ldg(H + (size_t)(n + 3) * 128 + f);
    }
    for (; n < n1; n++) a0 += __ldg(H + (size_t)n * 128 + f);
    g_pool_sum4[(chunk * N_GRAPHS + g) * 128 + f] = (a0 + a1) + (a2 + a3);
}

__global__ void k_head(const float* __restrict__ Wfc, const float* __restrict__ bfc,
                       float* __restrict__ out) {
    __shared__ float s_logit[N_GRAPHS][10];
    __shared__ float s_lse[N_GRAPHS];
    int tid = threadIdx.x;                   // 640 threads
    int g = tid / 10, j = tid % 10;
    float cnt = fmaxf((float)(g_gstart[g + 1] - g_gstart[g]), 1.f);
    float acc = bfc[j];
    #pragma unroll 8
    for (int f = 0; f < 128; f++) {
        float s = g_pool_sum4[(0 * N_GRAPHS + g) * 128 + f]
                + g_pool_sum4[(1 * N_GRAPHS + g) * 128 + f]
                + g_pool_sum4[(2 * N_GRAPHS + g) * 128 + f]
                + g_pool_sum4[(3 * N_GRAPHS + g) * 128 + f];
        acc += (s / cnt) * Wfc[f * 10 + j];
    }
    s_logit[g][j] = acc;
    __syncthreads();
    if (j == 0) {
        float m = -1e30f;
        #pragma unroll
        for (int t = 0; t < 10; t++) m = fmaxf(m, s_logit[g][t]);
        float s = 0.f;
        #pragma unroll
        for (int t = 0; t < 10; t++) s += expf(s_logit[g][t] - m);
        s_lse[g] = m + logf(s);
    }
    __syncthreads();
    out[g * 10 + j] = s_logit[g][j] - s_lse[g];
}

// ---------------- launch ----------------
extern "C" void kernel_launch(void* const* d_in, const int* in_sizes, int n_in,
                              void* d_out, int out_size) {
    const float* x   = (const float*)d_in[0];
    const float* W0  = (const float*)d_in[1];
    const float* b0  = (const float*)d_in[2];
    const float* W1  = (const float*)d_in[3];
    const float* b1  = (const float*)d_in[4];
    const float* W2  = (const float*)d_in[5];
    const float* b2  = (const float*)d_in[6];
    const float* W3  = (const float*)d_in[7];
    const float* b3  = (const float*)d_in[8];
    const float* Wfc = (const float*)d_in[9];
    const float* bfc = (const float*)d_in[10];
    const int* ei    = (const int*)d_in[11];
    const int* batch = (const int*)d_in[12];
    const int* src = ei;
    const int* dst = ei + N_EDGES;
    float* out = (float*)d_out;

    // CSR build
    k_zero<<<(N_NODES + 255) / 256, 256>>>();
    k_hist<<<(N_EDGES + 255) / 256, 256>>>(dst);
    k_scan1<<<NB_SCAN, SCAN_B>>>();
    k_scan2<<<1, 128>>>();
    k_scan3<<<NB_SCAN, SCAN_B>>>();
    k_fill<<<(N_EDGES + 255) / 256, 256>>>(src, dst);
    k_gstart<<<(N_NODES + 255) / 256, 256>>>(batch);

    int agg_blocks = (N_NODES * 32 + 255) / 256;
    dim3 g192((N_NODES + 127) / 128, 3);
    dim3 g128((N_NODES + 127) / 128, 2);

    // layer 1: x(128) -> agg(split bf16) -> gemm(128->192) -> g_bufC
    k_wprep<<<(128 * 192 + 255) / 256, 256>>>(W0, 128, 192);
    k_agg<128><<<agg_blocks, 256>>>(x);
    k_gemm<128, 192><<<g192, 256>>>(b0);
    // layer 2
    k_wprep<<<(192 * 192 + 255) / 256, 256>>>(W1, 192, 192);
    k_agg<192><<<agg_blocks, 256>>>(nullptr);
    k_gemm<192, 192><<<g192, 256>>>(b1);
    // layer 3
    k_wprep<<<(192 * 192 + 255) / 256, 256>>>(W2, 192, 192);
    k_agg<192><<<agg_blocks, 256>>>(nullptr);
    k_gemm<192, 192><<<g192, 256>>>(b2);
    // layer 4
    k_wprep<<<(192 * 128 + 255) / 256, 256>>>(W3, 192, 128);
    k_agg<192><<<agg_blocks, 256>>>(nullptr);
    k_gemm<192, 128><<<g128, 256>>>(b3);

    // pooling + head
    dim3 pool_grid(N_GRAPHS, 4);
    k_pool<<<pool_grid, 128>>>();
    k_head<<<1, 640>>>(Wfc, bfc, out);
}

// round 9
// speedup vs baseline: 1.2177x; 1.0186x over previous
#include <cuda_runtime.h>
#include <cuda_bf16.h>
#include <cuda_fp16.h>
#include <math.h>
#include <stdint.h>

#define N_NODES 100000
#define N_EDGES 1600000
#define N_GRAPHS 64
#define EPSF 1e-7f

#define SCAN_B 1024
#define NB_SCAN ((N_NODES + SCAN_B - 1) / SCAN_B)   // 98

// ---------------- scratch (device globals, device-side access ONLY) --------
__device__ int   g_deg[N_NODES];
__device__ int   g_rowstart[N_NODES];
__device__ int   g_cursor[N_NODES];
__device__ int   g_csr_src[N_EDGES];
__device__ int   g_blocksums[128];
__device__ int   g_gstart[N_GRAPHS + 1];
// fp32 GEMM output (layer i) -> residual/pool input
__device__ __align__(16) float g_bufC[(size_t)N_NODES * 192];
// fp16 copy of node features: GATHER source for agg (halved traffic).
// Written ONLY by k_xh (layer 1 input) and k_gemm epilogue (layers 2-4 input).
// k_agg only READS it -> no same-kernel read/write race.
__device__ __align__(16) __half g_h[(size_t)N_NODES * 192];
// split-bf16 activations (GEMM A operand), row stride = layer K
__device__ __align__(16) __nv_bfloat16 g_a1[(size_t)N_NODES * 192];
__device__ __align__(16) __nv_bfloat16 g_a2[(size_t)N_NODES * 192];
// split-bf16 transposed weights [DO][K]
__device__ __align__(16) __nv_bfloat16 g_w1t[192 * 192];
__device__ __align__(16) __nv_bfloat16 g_w2t[192 * 192];
// pool partials: [chunk][graph][feature], summed in head (no atomics)
__device__ float g_pool_sum4[4 * N_GRAPHS * 128];

__device__ __forceinline__ uint32_t packbf(float a, float b) {
    __nv_bfloat162 t = __floats2bfloat162_rn(a, b);
    return *(uint32_t*)&t;
}
__device__ __forceinline__ uint32_t packh(float a, float b) {
    __half2 t = __floats2half2_rn(a, b);
    return *(uint32_t*)&t;
}
__device__ __forceinline__ float2 h2f(uint32_t u) {
    return __half22float2(*(__half2*)&u);
}

// ---------------- CSR build ----------------
__global__ void k_zero() {
    int i = blockIdx.x * blockDim.x + threadIdx.x;
    if (i < N_NODES) g_deg[i] = 0;
}

__global__ void k_hist(const int* __restrict__ dst) {
    int i = blockIdx.x * blockDim.x + threadIdx.x;
    if (i < N_EDGES) atomicAdd(&g_deg[dst[i]], 1);
}

__global__ void k_scan1() {
    int idx = blockIdx.x * SCAN_B + threadIdx.x;
    int v = (idx < N_NODES) ? g_deg[idx] : 0;
    int lane = threadIdx.x & 31, w = threadIdx.x >> 5;
    int x = v;
    #pragma unroll
    for (int o = 1; o < 32; o <<= 1) {
        int t = __shfl_up_sync(0xffffffffu, x, o);
        if (lane >= o) x += t;
    }
    __shared__ int wsum[32];
    if (lane == 31) wsum[w] = x;
    __syncthreads();
    if (w == 0) {
        int y = wsum[lane];
        #pragma unroll
        for (int o = 1; o < 32; o <<= 1) {
            int t = __shfl_up_sync(0xffffffffu, y, o);
            if (lane >= o) y += t;
        }
        wsum[lane] = y;
    }
    __syncthreads();
    int incl = x + (w > 0 ? wsum[w - 1] : 0);
    if (idx < N_NODES) g_rowstart[idx] = incl - v;
    if (threadIdx.x == SCAN_B - 1) g_blocksums[blockIdx.x] = incl;
}

__global__ void k_scan2() {
    int t = threadIdx.x;
    int v = (t < NB_SCAN) ? g_blocksums[t] : 0;
    int lane = t & 31, w = t >> 5;
    int x = v;
    #pragma unroll
    for (int o = 1; o < 32; o <<= 1) {
        int tt = __shfl_up_sync(0xffffffffu, x, o);
        if (lane >= o) x += tt;
    }
    __shared__ int ws[4];
    if (lane == 31) ws[w] = x;
    __syncthreads();
    if (t == 0) {
        int a = 0;
        #pragma unroll
        for (int i = 0; i < 4; i++) { int tmp = ws[i]; ws[i] = a; a += tmp; }
    }
    __syncthreads();
    int incl = x + ws[w];
    if (t < 128) g_blocksums[t] = incl - v;
}

__global__ void k_scan3() {
    int idx = blockIdx.x * SCAN_B + threadIdx.x;
    if (idx < N_NODES) {
        int r = g_rowstart[idx] + g_blocksums[idx >> 10];
        g_rowstart[idx] = r;
        g_cursor[idx] = r;
    }
}

__global__ void k_fill(const int* __restrict__ src, const int* __restrict__ dst) {
    int i = blockIdx.x * blockDim.x + threadIdx.x;
    if (i < N_EDGES) {
        int p = atomicAdd(&g_cursor[dst[i]], 1);
        g_csr_src[p] = src[i];
    }
}

// graph boundaries from sorted batch: g_gstart[g] = first node of graph g
__global__ void k_gstart(const int* __restrict__ batch) {
    int i = blockIdx.x * blockDim.x + threadIdx.x;
    if (i >= N_NODES) return;
    int b = batch[i];
    int bp = (i == 0) ? -1 : batch[i - 1];
    for (int g = bp + 1; g <= b; g++) g_gstart[g] = i;
    if (i == N_NODES - 1)
        for (int g = b + 1; g <= N_GRAPHS; g++) g_gstart[g] = N_NODES;
}

// ---------------- fp16 copy of input x (layer-1 gather source) -------------
__global__ void k_xh(const float* __restrict__ x) {
    int i = blockIdx.x * blockDim.x + threadIdx.x;   // over N*128/4
    if (i < N_NODES * 128 / 4) {
        float4 v = __ldg((const float4*)x + i);
        uint2 o = make_uint2(packh(v.x, v.y), packh(v.z, v.w));
        *(uint2*)((char*)g_h + (size_t)i * 8) = o;
    }
}

// ---------------- aggregation: y = x + segsum(relu(h16[src])) + deg*eps ----
// one warp/node; gather from fp16 g_h (ONE load per edge, READ-ONLY);
// accumulate fp32; emits split-bf16 (GEMM A). Residual from xext/g_bufC.
template <int D>
__global__ void k_agg(const float* __restrict__ xext) {
    int gw = (blockIdx.x * blockDim.x + threadIdx.x) >> 5;
    if (gw >= N_NODES) return;
    int lane = threadIdx.x & 31;
    constexpr int FPL = (D == 192) ? 8 : 4;      // features per lane
    constexpr int ACT = D / FPL;                 // active lanes: 24 or 32
    const float* X = xext ? xext : (const float*)g_bufC;

    float acc[FPL];
    #pragma unroll
    for (int i = 0; i < FPL; i++) acc[i] = 0.f;

    int start = g_rowstart[gw];
    int deg = g_deg[gw];
    bool act = (lane < ACT);

    for (int base = 0; base < deg; base += 32) {
        int myidx = (base + lane < deg) ? g_csr_src[start + base + lane] : 0;
        int cnt = min(32, deg - base);
        for (int e = 0; e < cnt; e++) {
            int s = __shfl_sync(0xffffffffu, myidx, e);
            if (act) {
                const char* row = (const char*)g_h + (size_t)s * D * 2;
                if (D == 192) {
                    uint4 v = __ldg((const uint4*)(row + lane * 16));
                    float2 f0 = h2f(v.x), f1 = h2f(v.y), f2 = h2f(v.z), f3 = h2f(v.w);
                    acc[0] += fmaxf(f0.x, 0.f); acc[1] += fmaxf(f0.y, 0.f);
                    acc[2] += fmaxf(f1.x, 0.f); acc[3] += fmaxf(f1.y, 0.f);
                    acc[4] += fmaxf(f2.x, 0.f); acc[5] += fmaxf(f2.y, 0.f);
                    acc[6] += fmaxf(f3.x, 0.f); acc[7] += fmaxf(f3.y, 0.f);
                } else {
                    uint2 v = __ldg((const uint2*)(row + lane * 8));
                    float2 f0 = h2f(v.x), f1 = h2f(v.y);
                    acc[0] += fmaxf(f0.x, 0.f); acc[1] += fmaxf(f0.y, 0.f);
                    acc[2] += fmaxf(f1.x, 0.f); acc[3] += fmaxf(f1.y, 0.f);
                }
            }
        }
    }

    if (!act) return;
    float ep = (float)deg * EPSF;
    const float4* Xv = (const float4*)X;
    float y[FPL];
    #pragma unroll
    for (int q = 0; q < FPL / 4; q++) {
        float4 xv = __ldg(Xv + (size_t)gw * (D / 4) + lane * (FPL / 4) + q);
        y[q * 4 + 0] = xv.x + acc[q * 4 + 0] + ep;
        y[q * 4 + 1] = xv.y + acc[q * 4 + 1] + ep;
        y[q * 4 + 2] = xv.z + acc[q * 4 + 2] + ep;
        y[q * 4 + 3] = xv.w + acc[q * 4 + 3] + ep;
    }

    size_t fb = (size_t)gw * D + lane * FPL;     // feature index base
    if (D == 192) {
        uint32_t hi[4], lo[4];
        #pragma unroll
        for (int q = 0; q < 4; q++) {
            float a = y[q * 2], b = y[q * 2 + 1];
            hi[q] = packbf(a, b);
            float2 f = __bfloat1622float2(*(__nv_bfloat162*)&hi[q]);
            lo[q] = packbf(a - f.x, b - f.y);
        }
        *(uint4*)((char*)g_a1 + fb * 2) = make_uint4(hi[0], hi[1], hi[2], hi[3]);
        *(uint4*)((char*)g_a2 + fb * 2) = make_uint4(lo[0], lo[1], lo[2], lo[3]);
    } else {
        uint32_t h0 = packbf(y[0], y[1]), h1 = packbf(y[2], y[3]);
        float2 f0 = __bfloat1622float2(*(__nv_bfloat162*)&h0);
        float2 f1 = __bfloat1622float2(*(__nv_bfloat162*)&h1);
        uint32_t l0 = packbf(y[0] - f0.x, y[1] - f0.y);
        uint32_t l1 = packbf(y[2] - f1.x, y[3] - f1.y);
        *(uint2*)((char*)g_a1 + fb * 2) = make_uint2(h0, h1);
        *(uint2*)((char*)g_a2 + fb * 2) = make_uint2(l0, l1);
    }
}

// ---------------- weight prep: W[K,DO] f32 -> split bf16 [DO][K] -----------
__global__ void k_wprep(const float* __restrict__ W, int K, int DO) {
    int i = blockIdx.x * blockDim.x + threadIdx.x;
    if (i < K * DO) {
        int k = i / DO, n = i % DO;
        float w = W[i];
        __nv_bfloat16 h = __float2bfloat16(w);
        float r = w - __bfloat162float(h);
        g_w1t[n * K + k] = h;
        g_w2t[n * K + k] = __float2bfloat16(r);
    }
}

// ---------------- HMMA GEMM (R4-proven): C = (A1+A2) @ Wt + b --------------
// mma.sync m16n8k16 bf16, split x3. CTA 128x64, 8 warps (4Mx2N), warp 32x32.
// Epilogue writes fp32 C and the fp16 copy into g_h (next layer's gather).
#define MMA_BF16(d, a, b0_, b1_) \
    asm volatile("mma.sync.aligned.m16n8k16.row.col.f32.bf16.bf16.f32 " \
        "{%0,%1,%2,%3}, {%4,%5,%6,%7}, {%8,%9}, {%0,%1,%2,%3};" \
        : "+f"((d)[0]), "+f"((d)[1]), "+f"((d)[2]), "+f"((d)[3]) \
        : "r"((a)[0]), "r"((a)[1]), "r"((a)[2]), "r"((a)[3]), \
          "r"(b0_), "r"(b1_))

template <int K, int DO>
__global__ __launch_bounds__(256) void k_gemm(const float* __restrict__ bias) {
    float* C = g_bufC;
    __shared__ char As1[128 * 80];
    __shared__ char As2[128 * 80];
    __shared__ char Bs1[64 * 80];
    __shared__ char Bs2[64 * 80];

    int tid = threadIdx.x;
    int lane = tid & 31, wid = tid >> 5;
    int g = lane >> 2, t = lane & 3;
    int wm = wid & 3, wn = wid >> 2;
    int bm = blockIdx.x * 128;
    int bn = blockIdx.y * 64;

    float acc[2][4][4];
    #pragma unroll
    for (int i = 0; i < 2; i++)
        #pragma unroll
        for (int j = 0; j < 4; j++)
            #pragma unroll
            for (int q = 0; q < 4; q++) acc[i][j][q] = 0.f;

    constexpr int NCHUNK = K / 32;
    for (int c = 0; c < NCHUNK; c++) {
        #pragma unroll
        for (int i = 0; i < 2; i++) {
            int slot = tid * 2 + i;
            int row = slot >> 2, ch = slot & 3;
            int grow = bm + row;
            uint4 v1 = make_uint4(0, 0, 0, 0), v2 = v1;
            if (grow < N_NODES) {
                size_t gb = ((size_t)grow * K + c * 32) * 2 + ch * 16;
                v1 = __ldg((const uint4*)((const char*)g_a1 + gb));
                v2 = __ldg((const uint4*)((const char*)g_a2 + gb));
            }
            *(uint4*)(As1 + row * 80 + ch * 16) = v1;
            *(uint4*)(As2 + row * 80 + ch * 16) = v2;
        }
        {
            int n = tid >> 2, ch = tid & 3;
            size_t gb = ((size_t)(bn + n) * K + c * 32) * 2 + ch * 16;
            *(uint4*)(Bs1 + n * 80 + ch * 16) = __ldg((const uint4*)((const char*)g_w1t + gb));
            *(uint4*)(Bs2 + n * 80 + ch * 16) = __ldg((const uint4*)((const char*)g_w2t + gb));
        }
        __syncthreads();

        #pragma unroll
        for (int ks = 0; ks < 2; ks++) {
            int kb = ks * 32;
            uint32_t a1f[2][4], a2f[2][4];
            #pragma unroll
            for (int mt = 0; mt < 2; mt++) {
                int rb = (wm * 32 + mt * 16 + g) * 80 + kb + t * 4;
                a1f[mt][0] = *(const uint32_t*)(As1 + rb);
                a1f[mt][1] = *(const uint32_t*)(As1 + rb + 8 * 80);
                a1f[mt][2] = *(const uint32_t*)(As1 + rb + 16);
                a1f[mt][3] = *(const uint32_t*)(As1 + rb + 8 * 80 + 16);
                a2f[mt][0] = *(const uint32_t*)(As2 + rb);
                a2f[mt][1] = *(const uint32_t*)(As2 + rb + 8 * 80);
                a2f[mt][2] = *(const uint32_t*)(As2 + rb + 16);
                a2f[mt][3] = *(const uint32_t*)(As2 + rb + 8 * 80 + 16);
            }
            #pragma unroll
            for (int nt = 0; nt < 4; nt++) {
                int nb = (wn * 32 + nt * 8 + g) * 80 + kb + t * 4;
                uint32_t b10 = *(const uint32_t*)(Bs1 + nb);
                uint32_t b11 = *(const uint32_t*)(Bs1 + nb + 16);
                uint32_t b20 = *(const uint32_t*)(Bs2 + nb);
                uint32_t b21 = *(const uint32_t*)(Bs2 + nb + 16);
                #pragma unroll
                for (int mt = 0; mt < 2; mt++) {
                    MMA_BF16(acc[mt][nt], a1f[mt], b10, b11);
                    MMA_BF16(acc[mt][nt], a1f[mt], b20, b21);
                    MMA_BF16(acc[mt][nt], a2f[mt], b10, b11);
                }
            }
        }
        __syncthreads();
    }

    // epilogue: fp32 C + fp16 copy into g_h
    #pragma unroll
    for (int nt = 0; nt < 4; nt++) {
        int col = bn + wn * 32 + nt * 8 + 2 * t;
        float2 bv = *(const float2*)(bias + col);
        #pragma unroll
        for (int mt = 0; mt < 2; mt++) {
            int r0 = bm + wm * 32 + mt * 16 + g;
            if (r0 < N_NODES) {
                float2 o = make_float2(acc[mt][nt][0] + bv.x, acc[mt][nt][1] + bv.y);
                *(float2*)(C + (size_t)r0 * DO + col) = o;
                *(uint32_t*)((char*)g_h + ((size_t)r0 * DO + col) * 2) = packh(o.x, o.y);
            }
            int r1 = r0 + 8;
            if (r1 < N_NODES) {
                float2 o = make_float2(acc[mt][nt][2] + bv.x, acc[mt][nt][3] + bv.y);
                *(float2*)(C + (size_t)r1 * DO + col) = o;
                *(uint32_t*)((char*)g_h + ((size_t)r1 * DO + col) * 2) = packh(o.x, o.y);
            }
        }
    }
}

// ---------------- pooling (sorted batch -> segment sums, atomic-free) ------
__global__ void k_pool() {
    const float* H = g_bufC;                 // final layer output, d=128
    int g = blockIdx.x, chunk = blockIdx.y;  // 64 x 4
    int s = g_gstart[g], e = g_gstart[g + 1];
    int len = e - s;
    int n0 = s + (len * chunk) / 4;
    int n1 = s + (len * (chunk + 1)) / 4;
    int f = threadIdx.x;                     // 128 features
    float a0 = 0.f, a1 = 0.f, a2 = 0.f, a3 = 0.f;
    int n = n0;
    for (; n + 4 <= n1; n += 4) {
        a0 += __ldg(H + (size_t)(n + 0) * 128 + f);
        a1 += __ldg(H + (size_t)(n + 1) * 128 + f);
        a2 += __ldg(H + (size_t)(n + 2) * 128 + f);
        a3 += __ldg(H + (size_t)(n + 3) * 128 + f);
    }
    for (; n < n1; n++) a0 += __ldg(H + (size_t)n * 128 + f);
    g_pool_sum4[(chunk * N_GRAPHS + g) * 128 + f] = (a0 + a1) + (a2 + a3);
}

__global__ void k_head(const float* __restrict__ Wfc, const float* __restrict__ bfc,
                       float* __restrict__ out) {
    __shared__ float s_logit[N_GRAPHS][10];
    __shared__ float s_lse[N_GRAPHS];
    int tid = threadIdx.x;                   // 640 threads
    int g = tid / 10, j = tid % 10;
    float cnt = fmaxf((float)(g_gstart[g + 1] - g_gstart[g]), 1.f);
    float acc = bfc[j];
    #pragma unroll 8
    for (int f = 0; f < 128; f++) {
        float s = g_pool_sum4[(0 * N_GRAPHS + g) * 128 + f]
                + g_pool_sum4[(1 * N_GRAPHS + g) * 128 + f]
                + g_pool_sum4[(2 * N_GRAPHS + g) * 128 + f]
                + g_pool_sum4[(3 * N_GRAPHS + g) * 128 + f];
        acc += (s / cnt) * Wfc[f * 10 + j];
    }
    s_logit[g][j] = acc;
    __syncthreads();
    if (j == 0) {
        float m = -1e30f;
        #pragma unroll
        for (int t = 0; t < 10; t++) m = fmaxf(m, s_logit[g][t]);
        float s = 0.f;
        #pragma unroll
        for (int t = 0; t < 10; t++) s += expf(s_logit[g][t] - m);
        s_lse[g] = m + logf(s);
    }
    __syncthreads();
    out[g * 10 + j] = s_logit[g][j] - s_lse[g];
}

// ---------------- launch ----------------
extern "C" void kernel_launch(void* const* d_in, const int* in_sizes, int n_in,
                              void* d_out, int out_size) {
    const float* x   = (const float*)d_in[0];
    const float* W0  = (const float*)d_in[1];
    const float* b0  = (const float*)d_in[2];
    const float* W1  = (const float*)d_in[3];
    const float* b1  = (const float*)d_in[4];
    const float* W2  = (const float*)d_in[5];
    const float* b2  = (const float*)d_in[6];
    const float* W3  = (const float*)d_in[7];
    const float* b3  = (const float*)d_in[8];
    const float* Wfc = (const float*)d_in[9];
    const float* bfc = (const float*)d_in[10];
    const int* ei    = (const int*)d_in[11];
    const int* batch = (const int*)d_in[12];
    const int* src = ei;
    const int* dst = ei + N_EDGES;
    float* out = (float*)d_out;

    // CSR build
    k_zero<<<(N_NODES + 255) / 256, 256>>>();
    k_hist<<<(N_EDGES + 255) / 256, 256>>>(dst);
    k_scan1<<<NB_SCAN, SCAN_B>>>();
    k_scan2<<<1, 128>>>();
    k_scan3<<<NB_SCAN, SCAN_B>>>();
    k_fill<<<(N_EDGES + 255) / 256, 256>>>(src, dst);
    k_gstart<<<(N_NODES + 255) / 256, 256>>>(batch);
    k_xh<<<(N_NODES * 128 / 4 + 255) / 256, 256>>>(x);

    int agg_blocks = (N_NODES * 32 + 255) / 256;
    dim3 g192((N_NODES + 127) / 128, 3);
    dim3 g128((N_NODES + 127) / 128, 2);

    // layer 1: x(128) -> agg(split bf16) -> gemm(128->192) -> g_bufC (+g_h)
    k_wprep<<<(128 * 192 + 255) / 256, 256>>>(W0, 128, 192);
    k_agg<128><<<agg_blocks, 256>>>(x);
    k_gemm<128, 192><<<g192, 256>>>(b0);
    // layer 2
    k_wprep<<<(192 * 192 + 255) / 256, 256>>>(W1, 192, 192);
    k_agg<192><<<agg_blocks, 256>>>(nullptr);
    k_gemm<192, 192><<<g192, 256>>>(b1);
    // layer 3
    k_wprep<<<(192 * 192 + 255) / 256, 256>>>(W2, 192, 192);
    k_agg<192><<<agg_blocks, 256>>>(nullptr);
    k_gemm<192, 192><<<g192, 256>>>(b2);
    // layer 4
    k_wprep<<<(192 * 128 + 255) / 256, 256>>>(W3, 192, 128);
    k_agg<192><<<agg_blocks, 256>>>(nullptr);
    k_gemm<192, 128><<<g128, 256>>>(b3);

    // pooling + head
    dim3 pool_grid(N_GRAPHS, 4);
    k_pool<<<pool_grid, 128>>>();
    k_head<<<1, 640>>>(Wfc, bfc, out);
}

// round 10
// speedup vs baseline: 1.2308x; 1.0108x over previous
#include <cuda_runtime.h>
#include <cuda_bf16.h>
#include <cuda_fp16.h>
#include <math.h>
#include <stdint.h>

#define N_NODES 100000
#define N_EDGES 1600000
#define N_GRAPHS 64
#define EPSF 1e-7f

#define SCAN_B 1024
#define NB_SCAN ((N_NODES + SCAN_B - 1) / SCAN_B)   // 98

// ---------------- scratch (device globals, device-side access ONLY) --------
__device__ int   g_deg[N_NODES];
__device__ int   g_rowstart[N_NODES];
__device__ int   g_cursor[N_NODES];
__device__ int   g_csr_src[N_EDGES];
__device__ int   g_blocksums[128];
__device__ int   g_gstart[N_GRAPHS + 1];
// fp32 GEMM output (layer i) -> residual/pool input
__device__ __align__(16) float g_bufC[(size_t)N_NODES * 192];
// fp16 copy of node features: GATHER source for agg.
// Written ONLY by k_xh (layer 1) and k_gemm epilogue (layers 2-4); k_agg READ-ONLY.
__device__ __align__(16) __half g_h[(size_t)N_NODES * 192];
// split-bf16 activations (GEMM A operand), row stride = layer K
__device__ __align__(16) __nv_bfloat16 g_a1[(size_t)N_NODES * 192];
__device__ __align__(16) __nv_bfloat16 g_a2[(size_t)N_NODES * 192];
// split-bf16 transposed weights [DO][K]
__device__ __align__(16) __nv_bfloat16 g_w1t[192 * 192];
__device__ __align__(16) __nv_bfloat16 g_w2t[192 * 192];
// pool partials: [chunk][graph][feature], summed in head (no atomics)
__device__ float g_pool_sum4[4 * N_GRAPHS * 128];

__device__ __forceinline__ uint32_t packbf(float a, float b) {
    __nv_bfloat162 t = __floats2bfloat162_rn(a, b);
    return *(uint32_t*)&t;
}
__device__ __forceinline__ uint32_t packh(float a, float b) {
    __half2 t = __floats2half2_rn(a, b);
    return *(uint32_t*)&t;
}
__device__ __forceinline__ float2 h2f(uint32_t u) {
    return __half22float2(*(__half2*)&u);
}
// relu in packed fp16: max(v, 0)
__device__ __forceinline__ uint32_t hrelu2(uint32_t u) {
    __half2 z = *(__half2*)&(uint32_t){0u};
    __half2 r = __hmax2(*(__half2*)&u, z);
    return *(uint32_t*)&r;
}
__device__ __forceinline__ uint32_t hacc2(uint32_t a, uint32_t b) {
    __half2 r = __hadd2(*(__half2*)&a, *(__half2*)&b);
    return *(uint32_t*)&r;
}

// ---------------- CSR build ----------------
__global__ void k_zero() {
    int i = blockIdx.x * blockDim.x + threadIdx.x;
    if (i < N_NODES) g_deg[i] = 0;
}

__global__ void k_hist(const int* __restrict__ dst) {
    int i = blockIdx.x * blockDim.x + threadIdx.x;
    if (i < N_EDGES) atomicAdd(&g_deg[dst[i]], 1);
}

__global__ void k_scan1() {
    int idx = blockIdx.x * SCAN_B + threadIdx.x;
    int v = (idx < N_NODES) ? g_deg[idx] : 0;
    int lane = threadIdx.x & 31, w = threadIdx.x >> 5;
    int x = v;
    #pragma unroll
    for (int o = 1; o < 32; o <<= 1) {
        int t = __shfl_up_sync(0xffffffffu, x, o);
        if (lane >= o) x += t;
    }
    __shared__ int wsum[32];
    if (lane == 31) wsum[w] = x;
    __syncthreads();
    if (w == 0) {
        int y = wsum[lane];
        #pragma unroll
        for (int o = 1; o < 32; o <<= 1) {
            int t = __shfl_up_sync(0xffffffffu, y, o);
            if (lane >= o) y += t;
        }
        wsum[lane] = y;
    }
    __syncthreads();
    int incl = x + (w > 0 ? wsum[w - 1] : 0);
    if (idx < N_NODES) g_rowstart[idx] = incl - v;
    if (threadIdx.x == SCAN_B - 1) g_blocksums[blockIdx.x] = incl;
}

__global__ void k_scan2() {
    int t = threadIdx.x;
    int v = (t < NB_SCAN) ? g_blocksums[t] : 0;
    int lane = t & 31, w = t >> 5;
    int x = v;
    #pragma unroll
    for (int o = 1; o < 32; o <<= 1) {
        int tt = __shfl_up_sync(0xffffffffu, x, o);
        if (lane >= o) x += tt;
    }
    __shared__ int ws[4];
    if (lane == 31) ws[w] = x;
    __syncthreads();
    if (t == 0) {
        int a = 0;
        #pragma unroll
        for (int i = 0; i < 4; i++) { int tmp = ws[i]; ws[i] = a; a += tmp; }
    }
    __syncthreads();
    int incl = x + ws[w];
    if (t < 128) g_blocksums[t] = incl - v;
}

__global__ void k_scan3() {
    int idx = blockIdx.x * SCAN_B + threadIdx.x;
    if (idx < N_NODES) {
        int r = g_rowstart[idx] + g_blocksums[idx >> 10];
        g_rowstart[idx] = r;
        g_cursor[idx] = r;
    }
}

__global__ void k_fill(const int* __restrict__ src, const int* __restrict__ dst) {
    int i = blockIdx.x * blockDim.x + threadIdx.x;
    if (i < N_EDGES) {
        int p = atomicAdd(&g_cursor[dst[i]], 1);
        g_csr_src[p] = src[i];
    }
}

// graph boundaries from sorted batch: g_gstart[g] = first node of graph g
__global__ void k_gstart(const int* __restrict__ batch) {
    int i = blockIdx.x * blockDim.x + threadIdx.x;
    if (i >= N_NODES) return;
    int b = batch[i];
    int bp = (i == 0) ? -1 : batch[i - 1];
    for (int g = bp + 1; g <= b; g++) g_gstart[g] = i;
    if (i == N_NODES - 1)
        for (int g = b + 1; g <= N_GRAPHS; g++) g_gstart[g] = N_NODES;
}

// ---------------- fp16 copy of input x (layer-1 gather source) -------------
__global__ void k_xh(const float* __restrict__ x) {
    int i = blockIdx.x * blockDim.x + threadIdx.x;   // over N*128/4
    if (i < N_NODES * 128 / 4) {
        float4 v = __ldg((const float4*)x + i);
        uint2 o = make_uint2(packh(v.x, v.y), packh(v.z, v.w));
        *(uint2*)((char*)g_h + (size_t)i * 8) = o;
    }
}

// ---------------- aggregation: y = x + segsum(relu(h16[src])) + deg*eps ----
// one warp/node; gather from fp16 g_h (READ-ONLY).
// Inner loop: packed HMAX2/HADD2 on groups of 4 edges, fp32 flush per group.
template <int D>
__global__ void k_agg(const float* __restrict__ xext) {
    int gw = (blockIdx.x * blockDim.x + threadIdx.x) >> 5;
    if (gw >= N_NODES) return;
    int lane = threadIdx.x & 31;
    constexpr int FPL = (D == 192) ? 8 : 4;      // features per lane
    constexpr int ACT = D / FPL;                 // active lanes: 24 or 32
    constexpr int NH = FPL / 2;                  // half2 accumulators: 4 or 2
    const float* X = xext ? xext : (const float*)g_bufC;

    float accf[FPL];
    #pragma unroll
    for (int i = 0; i < FPL; i++) accf[i] = 0.f;

    int start = g_rowstart[gw];
    int deg = g_deg[gw];
    bool act = (lane < ACT);

    for (int base = 0; base < deg; base += 32) {
        int myidx = (base + lane < deg) ? g_csr_src[start + base + lane] : 0;
        int cnt = min(32, deg - base);
        for (int e = 0; e < cnt; e += 4) {
            uint32_t acch[NH];
            #pragma unroll
            for (int j = 0; j < NH; j++) acch[j] = 0u;
            #pragma unroll
            for (int k = 0; k < 4; k++) {
                int idx = e + k;
                int sl = (idx < cnt) ? idx : (cnt - 1);
                int s = __shfl_sync(0xffffffffu, myidx, sl);
                if (act && idx < cnt) {
                    const char* row = (const char*)g_h + (size_t)s * D * 2;
                    if (D == 192) {
                        uint4 v = __ldg((const uint4*)(row + lane * 16));
                        acch[0] = hacc2(acch[0], hrelu2(v.x));
                        acch[1] = hacc2(acch[1], hrelu2(v.y));
                        acch[2] = hacc2(acch[2], hrelu2(v.z));
                        acch[3] = hacc2(acch[3], hrelu2(v.w));
                    } else {
                        uint2 v = __ldg((const uint2*)(row + lane * 8));
                        acch[0] = hacc2(acch[0], hrelu2(v.x));
                        acch[1] = hacc2(acch[1], hrelu2(v.y));
                    }
                }
            }
            // flush 4-edge fp16 partials into fp32 accumulators
            #pragma unroll
            for (int j = 0; j < NH; j++) {
                float2 f = h2f(acch[j]);
                accf[j * 2 + 0] += f.x;
                accf[j * 2 + 1] += f.y;
            }
        }
    }

    if (!act) return;
    float ep = (float)deg * EPSF;
    const float4* Xv = (const float4*)X;
    float y[FPL];
    #pragma unroll
    for (int q = 0; q < FPL / 4; q++) {
        float4 xv = __ldg(Xv + (size_t)gw * (D / 4) + lane * (FPL / 4) + q);
        y[q * 4 + 0] = xv.x + accf[q * 4 + 0] + ep;
        y[q * 4 + 1] = xv.y + accf[q * 4 + 1] + ep;
        y[q * 4 + 2] = xv.z + accf[q * 4 + 2] + ep;
        y[q * 4 + 3] = xv.w + accf[q * 4 + 3] + ep;
    }

    size_t fb = (size_t)gw * D + lane * FPL;     // feature index base
    if (D == 192) {
        uint32_t hi[4], lo[4];
        #pragma unroll
        for (int q = 0; q < 4; q++) {
            float a = y[q * 2], b = y[q * 2 + 1];
            hi[q] = packbf(a, b);
            float2 f = __bfloat1622float2(*(__nv_bfloat162*)&hi[q]);
            lo[q] = packbf(a - f.x, b - f.y);
        }
        *(uint4*)((char*)g_a1 + fb * 2) = make_uint4(hi[0], hi[1], hi[2], hi[3]);
        *(uint4*)((char*)g_a2 + fb * 2) = make_uint4(lo[0], lo[1], lo[2], lo[3]);
    } else {
        uint32_t h0 = packbf(y[0], y[1]), h1 = packbf(y[2], y[3]);
        float2 f0 = __bfloat1622float2(*(__nv_bfloat162*)&h0);
        float2 f1 = __bfloat1622float2(*(__nv_bfloat162*)&h1);
        uint32_t l0 = packbf(y[0] - f0.x, y[1] - f0.y);
        uint32_t l1 = packbf(y[2] - f1.x, y[3] - f1.y);
        *(uint2*)((char*)g_a1 + fb * 2) = make_uint2(h0, h1);
        *(uint2*)((char*)g_a2 + fb * 2) = make_uint2(l0, l1);
    }
}

// ---------------- weight prep: W[K,DO] f32 -> split bf16 [DO][K] -----------
__global__ void k_wprep(const float* __restrict__ W, int K, int DO) {
    int i = blockIdx.x * blockDim.x + threadIdx.x;
    if (i < K * DO) {
        int k = i / DO, n = i % DO;
        float w = W[i];
        __nv_bfloat16 h = __float2bfloat16(w);
        float r = w - __bfloat162float(h);
        g_w1t[n * K + k] = h;
        g_w2t[n * K + k] = __float2bfloat16(r);
    }
}

// ---------------- HMMA GEMM (R4-proven): C = (A1+A2) @ Wt + b --------------
// mma.sync m16n8k16 bf16, split x3. CTA 128x64, 8 warps (4Mx2N), warp 32x32.
// Epilogue writes fp32 C and the fp16 copy into g_h (next layer's gather).
#define MMA_BF16(d, a, b0_, b1_) \
    asm volatile("mma.sync.aligned.m16n8k16.row.col.f32.bf16.bf16.f32 " \
        "{%0,%1,%2,%3}, {%4,%5,%6,%7}, {%8,%9}, {%0,%1,%2,%3};" \
        : "+f"((d)[0]), "+f"((d)[1]), "+f"((d)[2]), "+f"((d)[3]) \
        : "r"((a)[0]), "r"((a)[1]), "r"((a)[2]), "r"((a)[3]), \
          "r"(b0_), "r"(b1_))

template <int K, int DO>
__global__ __launch_bounds__(256) void k_gemm(const float* __restrict__ bias) {
    float* C = g_bufC;
    __shared__ char As1[128 * 80];
    __shared__ char As2[128 * 80];
    __shared__ char Bs1[64 * 80];
    __shared__ char Bs2[64 * 80];

    int tid = threadIdx.x;
    int lane = tid & 31, wid = tid >> 5;
    int g = lane >> 2, t = lane & 3;
    int wm = wid & 3, wn = wid >> 2;
    int bm = blockIdx.x * 128;
    int bn = blockIdx.y * 64;

    float acc[2][4][4];
    #pragma unroll
    for (int i = 0; i < 2; i++)
        #pragma unroll
        for (int j = 0; j < 4; j++)
            #pragma unroll
            for (int q = 0; q < 4; q++) acc[i][j][q] = 0.f;

    constexpr int NCHUNK = K / 32;
    for (int c = 0; c < NCHUNK; c++) {
        #pragma unroll
        for (int i = 0; i < 2; i++) {
            int slot = tid * 2 + i;
            int row = slot >> 2, ch = slot & 3;
            int grow = bm + row;
            uint4 v1 = make_uint4(0, 0, 0, 0), v2 = v1;
            if (grow < N_NODES) {
                size_t gb = ((size_t)grow * K + c * 32) * 2 + ch * 16;
                v1 = __ldg((const uint4*)((const char*)g_a1 + gb));
                v2 = __ldg((const uint4*)((const char*)g_a2 + gb));
            }
            *(uint4*)(As1 + row * 80 + ch * 16) = v1;
            *(uint4*)(As2 + row * 80 + ch * 16) = v2;
        }
        {
            int n = tid >> 2, ch = tid & 3;
            size_t gb = ((size_t)(bn + n) * K + c * 32) * 2 + ch * 16;
            *(uint4*)(Bs1 + n * 80 + ch * 16) = __ldg((const uint4*)((const char*)g_w1t + gb));
            *(uint4*)(Bs2 + n * 80 + ch * 16) = __ldg((const uint4*)((const char*)g_w2t + gb));
        }
        __syncthreads();

        #pragma unroll
        for (int ks = 0; ks < 2; ks++) {
            int kb = ks * 32;
            uint32_t a1f[2][4], a2f[2][4];
            #pragma unroll
            for (int mt = 0; mt < 2; mt++) {
                int rb = (wm * 32 + mt * 16 + g) * 80 + kb + t * 4;
                a1f[mt][0] = *(const uint32_t*)(As1 + rb);
                a1f[mt][1] = *(const uint32_t*)(As1 + rb + 8 * 80);
                a1f[mt][2] = *(const uint32_t*)(As1 + rb + 16);
                a1f[mt][3] = *(const uint32_t*)(As1 + rb + 8 * 80 + 16);
                a2f[mt][0] = *(const uint32_t*)(As2 + rb);
                a2f[mt][1] = *(const uint32_t*)(As2 + rb + 8 * 80);
                a2f[mt][2] = *(const uint32_t*)(As2 + rb + 16);
                a2f[mt][3] = *(const uint32_t*)(As2 + rb + 8 * 80 + 16);
            }
            #pragma unroll
            for (int nt = 0; nt < 4; nt++) {
                int nb = (wn * 32 + nt * 8 + g) * 80 + kb + t * 4;
                uint32_t b10 = *(const uint32_t*)(Bs1 + nb);
                uint32_t b11 = *(const uint32_t*)(Bs1 + nb + 16);
                uint32_t b20 = *(const uint32_t*)(Bs2 + nb);
                uint32_t b21 = *(const uint32_t*)(Bs2 + nb + 16);
                #pragma unroll
                for (int mt = 0; mt < 2; mt++) {
                    MMA_BF16(acc[mt][nt], a1f[mt], b10, b11);
                    MMA_BF16(acc[mt][nt], a1f[mt], b20, b21);
                    MMA_BF16(acc[mt][nt], a2f[mt], b10, b11);
                }
            }
        }
        __syncthreads();
    }

    // epilogue: fp32 C + fp16 copy into g_h
    #pragma unroll
    for (int nt = 0; nt < 4; nt++) {
        int col = bn + wn * 32 + nt * 8 + 2 * t;
        float2 bv = *(const float2*)(bias + col);
        #pragma unroll
        for (int mt = 0; mt < 2; mt++) {
            int r0 = bm + wm * 32 + mt * 16 + g;
            if (r0 < N_NODES) {
                float2 o = make_float2(acc[mt][nt][0] + bv.x, acc[mt][nt][1] + bv.y);
                *(float2*)(C + (size_t)r0 * DO + col) = o;
                *(uint32_t*)((char*)g_h + ((size_t)r0 * DO + col) * 2) = packh(o.x, o.y);
            }
            int r1 = r0 + 8;
            if (r1 < N_NODES) {
                float2 o = make_float2(acc[mt][nt][2] + bv.x, acc[mt][nt][3] + bv.y);
                *(float2*)(C + (size_t)r1 * DO + col) = o;
                *(uint32_t*)((char*)g_h + ((size_t)r1 * DO + col) * 2) = packh(o.x, o.y);
            }
        }
    }
}

// ---------------- pooling (sorted batch -> segment sums, atomic-free) ------
__global__ void k_pool() {
    const float* H = g_bufC;                 // final layer output, d=128
    int g = blockIdx.x, chunk = blockIdx.y;  // 64 x 4
    int s = g_gstart[g], e = g_gstart[g + 1];
    int len = e - s;
    int n0 = s + (len * chunk) / 4;
    int n1 = s + (len * (chunk + 1)) / 4;
    int f = threadIdx.x;                     // 128 features
    float a0 = 0.f, a1 = 0.f, a2 = 0.f, a3 = 0.f;
    int n = n0;
    for (; n + 4 <= n1; n += 4) {
        a0 += __ldg(H + (size_t)(n + 0) * 128 + f);
        a1 += __ldg(H + (size_t)(n + 1) * 128 + f);
        a2 += __ldg(H + (size_t)(n + 2) * 128 + f);
        a3 += __ldg(H + (size_t)(n + 3) * 128 + f);
    }
    for (; n < n1; n++) a0 += __ldg(H + (size_t)n * 128 + f);
    g_pool_sum4[(chunk * N_GRAPHS + g) * 128 + f] = (a0 + a1) + (a2 + a3);
}

__global__ void k_head(const float* __restrict__ Wfc, const float* __restrict__ bfc,
                       float* __restrict__ out) {
    __shared__ float s_logit[N_GRAPHS][10];
    __shared__ float s_lse[N_GRAPHS];
    int tid = threadIdx.x;                   // 640 threads
    int g = tid / 10, j = tid % 10;
    float cnt = fmaxf((float)(g_gstart[g + 1] - g_gstart[g]), 1.f);
    float acc = bfc[j];
    #pragma unroll 8
    for (int f = 0; f < 128; f++) {
        float s = g_pool_sum4[(0 * N_GRAPHS + g) * 128 + f]
                + g_pool_sum4[(1 * N_GRAPHS + g) * 128 + f]
                + g_pool_sum4[(2 * N_GRAPHS + g) * 128 + f]
                + g_pool_sum4[(3 * N_GRAPHS + g) * 128 + f];
        acc += (s / cnt) * Wfc[f * 10 + j];
    }
    s_logit[g][j] = acc;
    __syncthreads();
    if (j == 0) {
        float m = -1e30f;
        #pragma unroll
        for (int t = 0; t < 10; t++) m = fmaxf(m, s_logit[g][t]);
        float s = 0.f;
        #pragma unroll
        for (int t = 0; t < 10; t++) s += expf(s_logit[g][t] - m);
        s_lse[g] = m + logf(s);
    }
    __syncthreads();
    out[g * 10 + j] = s_logit[g][j] - s_lse[g];
}

// ---------------- launch ----------------
extern "C" void kernel_launch(void* const* d_in, const int* in_sizes, int n_in,
                              void* d_out, int out_size) {
    const float* x   = (const float*)d_in[0];
    const float* W0  = (const float*)d_in[1];
    const float* b0  = (const float*)d_in[2];
    const float* W1  = (const float*)d_in[3];
    const float* b1  = (const float*)d_in[4];
    const float* W2  = (const float*)d_in[5];
    const float* b2  = (const float*)d_in[6];
    const float* W3  = (const float*)d_in[7];
    const float* b3  = (const float*)d_in[8];
    const float* Wfc = (const float*)d_in[9];
    const float* bfc = (const float*)d_in[10];
    const int* ei    = (const int*)d_in[11];
    const int* batch = (const int*)d_in[12];
    const int* src = ei;
    const int* dst = ei + N_EDGES;
    float* out = (float*)d_out;

    // CSR build
    k_zero<<<(N_NODES + 255) / 256, 256>>>();
    k_hist<<<(N_EDGES + 255) / 256, 256>>>(dst);
    k_scan1<<<NB_SCAN, SCAN_B>>>();
    k_scan2<<<1, 128>>>();
    k_scan3<<<NB_SCAN, SCAN_B>>>();
    k_fill<<<(N_EDGES + 255) / 256, 256>>>(src, dst);
    k_gstart<<<(N_NODES + 255) / 256, 256>>>(batch);
    k_xh<<<(N_NODES * 128 / 4 + 255) / 256, 256>>>(x);

    int agg_blocks = (N_NODES * 32 + 255) / 256;
    dim3 g192((N_NODES + 127) / 128, 3);
    dim3 g128((N_NODES + 127) / 128, 2);

    // layer 1: x(128) -> agg(split bf16) -> gemm(128->192) -> g_bufC (+g_h)
    k_wprep<<<(128 * 192 + 255) / 256, 256>>>(W0, 128, 192);
    k_agg<128><<<agg_blocks, 256>>>(x);
    k_gemm<128, 192><<<g192, 256>>>(b0);
    // layer 2
    k_wprep<<<(192 * 192 + 255) / 256, 256>>>(W1, 192, 192);
    k_agg<192><<<agg_blocks, 256>>>(nullptr);
    k_gemm<192, 192><<<g192, 256>>>(b1);
    // layer 3
    k_wprep<<<(192 * 192 + 255) / 256, 256>>>(W2, 192, 192);
    k_agg<192><<<agg_blocks, 256>>>(nullptr);
    k_gemm<192, 192><<<g192, 256>>>(b2);
    // layer 4
    k_wprep<<<(192 * 128 + 255) / 256, 256>>>(W3, 192, 128);
    k_agg<192><<<agg_blocks, 256>>>(nullptr);
    k_gemm<192, 128><<<g128, 256>>>(b3);

    // pooling + head
    dim3 pool_grid(N_GRAPHS, 4);
    k_pool<<<pool_grid, 128>>>();
    k_head<<<1, 640>>>(Wfc, bfc, out);
}